// round 1
// baseline (speedup 1.0000x reference)
#include <cuda_runtime.h>
#include <math.h>

#define B_ 8
#define T_ 2048
#define D_ 1024
#define H_ 128
#define SCALE 0.08838834764831845f   // 1/sqrt(128)

// Scratch for q, k, v projections: [B*T, H] each (8 MB each)
__device__ float g_q[(size_t)B_ * T_ * H_];
__device__ float g_k[(size_t)B_ * T_ * H_];
__device__ float g_v[(size_t)B_ * T_ * H_];

// ---------------------------------------------------------------------------
// Kernel 1: fused QKV projection.  Y = X[16384,1024] @ W[1024,128]
// grid (128, 3): blockIdx.x = 128-row M tile, blockIdx.y selects Wq/Wk/Wv.
// Classic 128x128x16 SGEMM tile, 256 threads, 8x8 per-thread microtile.
// ---------------------------------------------------------------------------
__global__ __launch_bounds__(256) void qkv_kernel(
    const float* __restrict__ x,
    const float* __restrict__ Wq,
    const float* __restrict__ Wk,
    const float* __restrict__ Wv)
{
    __shared__ float As[16][132];   // [k][m], padded stride
    __shared__ float Bs[16][132];   // [k][n]

    const float* W  = (blockIdx.y == 0) ? Wq : (blockIdx.y == 1 ? Wk : Wv);
    float*      out = (blockIdx.y == 0) ? g_q : (blockIdx.y == 1 ? g_k : g_v);

    const int m0  = blockIdx.x * 128;
    const int tid = threadIdx.x;
    const int ty  = tid >> 4, tx = tid & 15;
    const int lr  = tid >> 2, lc = (tid & 3) * 4;   // X tile load: 64 rows x 16 cols, x2
    const int wr  = tid >> 5, wc = (tid & 31) * 4;  // W tile load: 8 rows x 128 cols, x2

    float acc[8][8];
#pragma unroll
    for (int i = 0; i < 8; i++)
#pragma unroll
        for (int j = 0; j < 8; j++) acc[i][j] = 0.f;

    for (int k0 = 0; k0 < D_; k0 += 16) {
        float4 xa = *(const float4*)(x + (size_t)(m0 + lr)      * D_ + k0 + lc);
        float4 xb = *(const float4*)(x + (size_t)(m0 + lr + 64) * D_ + k0 + lc);
        float4 wa = *(const float4*)(W + (size_t)(k0 + wr)     * H_ + wc);
        float4 wb = *(const float4*)(W + (size_t)(k0 + wr + 8) * H_ + wc);
        __syncthreads();
        As[lc + 0][lr] = xa.x; As[lc + 1][lr] = xa.y;
        As[lc + 2][lr] = xa.z; As[lc + 3][lr] = xa.w;
        As[lc + 0][lr + 64] = xb.x; As[lc + 1][lr + 64] = xb.y;
        As[lc + 2][lr + 64] = xb.z; As[lc + 3][lr + 64] = xb.w;
        *(float4*)&Bs[wr][wc]     = wa;
        *(float4*)&Bs[wr + 8][wc] = wb;
        __syncthreads();
#pragma unroll
        for (int kk = 0; kk < 16; kk++) {
            float4 a0 = *(float4*)&As[kk][ty * 4];
            float4 a1 = *(float4*)&As[kk][64 + ty * 4];
            float4 b0 = *(float4*)&Bs[kk][tx * 4];
            float4 b1 = *(float4*)&Bs[kk][64 + tx * 4];
            float a[8] = {a0.x, a0.y, a0.z, a0.w, a1.x, a1.y, a1.z, a1.w};
            float b[8] = {b0.x, b0.y, b0.z, b0.w, b1.x, b1.y, b1.z, b1.w};
#pragma unroll
            for (int i = 0; i < 8; i++)
#pragma unroll
                for (int j = 0; j < 8; j++)
                    acc[i][j] = fmaf(a[i], b[j], acc[i][j]);
        }
    }

#pragma unroll
    for (int i = 0; i < 8; i++) {
        int row = m0 + ((i < 4) ? (ty * 4 + i) : (64 + ty * 4 + i - 4));
        float4 c0 = make_float4(acc[i][0], acc[i][1], acc[i][2], acc[i][3]);
        float4 c1 = make_float4(acc[i][4], acc[i][5], acc[i][6], acc[i][7]);
        *(float4*)(out + (size_t)row * H_ + tx * 4)      = c0;
        *(float4*)(out + (size_t)row * H_ + 64 + tx * 4) = c1;
    }
}

// ---------------------------------------------------------------------------
// Kernel 2: causal flash attention, fp32, BQ = BK = 64.
// grid (16, 8): blockIdx.y = batch; block handles q-tiles x and 31-x
// (pairing => every block does exactly 33 k-tiles: perfect load balance).
// 256 threads. S phase: 16x16 thread grid, 4x4 per thread.
// PV phase: 4 rows x 8 cols per thread (split as cg*4 and 64+cg*4).
// ---------------------------------------------------------------------------
#define QSTRIDE 132
#define PSTRIDE 65
#define SM_Q 0
#define SM_K (64 * QSTRIDE)
#define SM_V (2 * 64 * QSTRIDE)
#define SM_P (3 * 64 * QSTRIDE)
#define SM_M (SM_P + 64 * PSTRIDE)
#define SM_L (SM_M + 64)
#define SM_C (SM_L + 64)
#define SMEM_FLOATS (SM_C + 64)
#define SMEM_BYTES (SMEM_FLOATS * 4)

__global__ __launch_bounds__(256, 1) void attn_kernel(float* __restrict__ out)
{
    extern __shared__ float sm[];
    float* Qs  = sm + SM_Q;
    float* Ks  = sm + SM_K;
    float* Vs  = sm + SM_V;
    float* Ps  = sm + SM_P;
    float* m_s = sm + SM_M;
    float* l_s = sm + SM_L;
    float* c_s = sm + SM_C;

    const int tid = threadIdx.x;
    const int b   = blockIdx.y;
    const int ty  = tid >> 4, tx = tid & 15;   // S mapping
    const int rg  = ty,       cg = tx;         // PV mapping

    for (int pass = 0; pass < 2; pass++) {
        const int qt = pass ? (31 - (int)blockIdx.x) : (int)blockIdx.x;
        const size_t qbase = ((size_t)b * T_ + (size_t)qt * 64) * H_;

        __syncthreads();                       // guard smem reuse across passes
        if (tid < 64) { m_s[tid] = -INFINITY; l_s[tid] = 0.f; }
        for (int i = tid; i < 64 * 32; i += 256) {
            int r = i >> 5, c = (i & 31) * 4;
            *(float4*)&Qs[r * QSTRIDE + c] =
                *(const float4*)(g_q + qbase + (size_t)r * H_ + c);
        }
        float o[4][8];
#pragma unroll
        for (int i = 0; i < 4; i++)
#pragma unroll
            for (int j = 0; j < 8; j++) o[i][j] = 0.f;
        __syncthreads();

        for (int kt = 0; kt <= qt; kt++) {
            const size_t kbase = ((size_t)b * T_ + (size_t)kt * 64) * H_;
            for (int i = tid; i < 64 * 32; i += 256) {
                int r = i >> 5, c = (i & 31) * 4;
                *(float4*)&Ks[r * QSTRIDE + c] =
                    *(const float4*)(g_k + kbase + (size_t)r * H_ + c);
                *(float4*)&Vs[r * QSTRIDE + c] =
                    *(const float4*)(g_v + kbase + (size_t)r * H_ + c);
            }
            __syncthreads();

            // ---- S = Q K^T (4x4 per thread) ----
            float s[4][4];
#pragma unroll
            for (int i = 0; i < 4; i++)
#pragma unroll
                for (int j = 0; j < 4; j++) s[i][j] = 0.f;

            for (int kk = 0; kk < 128; kk += 4) {
                float4 qv[4], kv[4];
#pragma unroll
                for (int i = 0; i < 4; i++)
                    qv[i] = *(float4*)&Qs[(ty * 4 + i) * QSTRIDE + kk];
#pragma unroll
                for (int j = 0; j < 4; j++)
                    kv[j] = *(float4*)&Ks[(tx * 4 + j) * QSTRIDE + kk];
#pragma unroll
                for (int i = 0; i < 4; i++)
#pragma unroll
                    for (int j = 0; j < 4; j++) {
                        s[i][j] = fmaf(qv[i].x, kv[j].x, s[i][j]);
                        s[i][j] = fmaf(qv[i].y, kv[j].y, s[i][j]);
                        s[i][j] = fmaf(qv[i].z, kv[j].z, s[i][j]);
                        s[i][j] = fmaf(qv[i].w, kv[j].w, s[i][j]);
                    }
            }

            // ---- online softmax (per row, 16-lane reductions) ----
#pragma unroll
            for (int i = 0; i < 4; i++) {
                const int r = ty * 4 + i;
                float rm = -INFINITY;
                float sc[4];
#pragma unroll
                for (int j = 0; j < 4; j++) {
                    float v = s[i][j] * SCALE;
                    if (kt == qt && (tx * 4 + j) > r) v = -INFINITY;
                    sc[j] = v;
                    rm = fmaxf(rm, v);
                }
#pragma unroll
                for (int d = 1; d < 16; d <<= 1)
                    rm = fmaxf(rm, __shfl_xor_sync(0xffffffffu, rm, d));
                const float mold = m_s[r];
                const float mnew = fmaxf(mold, rm);
                float rs = 0.f;
#pragma unroll
                for (int j = 0; j < 4; j++) {
                    float p = __expf(sc[j] - mnew);
                    Ps[r * PSTRIDE + tx * 4 + j] = p;
                    rs += p;
                }
#pragma unroll
                for (int d = 1; d < 16; d <<= 1)
                    rs += __shfl_xor_sync(0xffffffffu, rs, d);
                if (tx == 0) {
                    float corr = __expf(mold - mnew);
                    c_s[r] = corr;
                    l_s[r] = l_s[r] * corr + rs;
                    m_s[r] = mnew;
                }
            }
            __syncthreads();

            // ---- O = O*corr + P @ V  (4 rows x 8 cols per thread) ----
            float corr[4];
#pragma unroll
            for (int i = 0; i < 4; i++) {
                corr[i] = c_s[rg * 4 + i];
#pragma unroll
                for (int j = 0; j < 8; j++) o[i][j] *= corr[i];
            }
            for (int j2 = 0; j2 < 64; j2++) {
                float4 v0 = *(float4*)&Vs[j2 * QSTRIDE + cg * 4];
                float4 v1 = *(float4*)&Vs[j2 * QSTRIDE + 64 + cg * 4];
#pragma unroll
                for (int i = 0; i < 4; i++) {
                    float p = Ps[(rg * 4 + i) * PSTRIDE + j2];
                    o[i][0] = fmaf(p, v0.x, o[i][0]);
                    o[i][1] = fmaf(p, v0.y, o[i][1]);
                    o[i][2] = fmaf(p, v0.z, o[i][2]);
                    o[i][3] = fmaf(p, v0.w, o[i][3]);
                    o[i][4] = fmaf(p, v1.x, o[i][4]);
                    o[i][5] = fmaf(p, v1.y, o[i][5]);
                    o[i][6] = fmaf(p, v1.z, o[i][6]);
                    o[i][7] = fmaf(p, v1.w, o[i][7]);
                }
            }
            __syncthreads();   // before next kt overwrites Ks/Vs/Ps/stats
        }

        // ---- epilogue: normalize and store ----
#pragma unroll
        for (int i = 0; i < 4; i++) {
            const int r = rg * 4 + i;
            const float inv = 1.f / l_s[r];
            float4 c0 = make_float4(o[i][0] * inv, o[i][1] * inv,
                                    o[i][2] * inv, o[i][3] * inv);
            float4 c1 = make_float4(o[i][4] * inv, o[i][5] * inv,
                                    o[i][6] * inv, o[i][7] * inv);
            float* dst = out + qbase + (size_t)r * H_;
            *(float4*)(dst + cg * 4)      = c0;
            *(float4*)(dst + 64 + cg * 4) = c1;
        }
    }
}

// ---------------------------------------------------------------------------
extern "C" void kernel_launch(void* const* d_in, const int* in_sizes, int n_in,
                              void* d_out, int out_size)
{
    const float* x  = (const float*)d_in[0];
    const float* Wq = (const float*)d_in[1];
    const float* Wk = (const float*)d_in[2];
    const float* Wv = (const float*)d_in[3];
    float* out = (float*)d_out;

    qkv_kernel<<<dim3(128, 3), 256>>>(x, Wq, Wk, Wv);

    cudaFuncSetAttribute(attn_kernel,
                         cudaFuncAttributeMaxDynamicSharedMemorySize,
                         SMEM_BYTES);
    attn_kernel<<<dim3(16, 8), 256, SMEM_BYTES>>>(out);
}

// round 2
// speedup vs baseline: 1.4246x; 1.4246x over previous
#include <cuda_runtime.h>
#include <math.h>

#define B_ 8
#define T_ 2048
#define D_ 1024
#define H_ 128
#define SCALE 0.08838834764831845f   // 1/sqrt(128)

typedef unsigned long long u64;

// ---- f32x2 packed helpers (sm_103a: FFMA2 only reachable via PTX) ----
__device__ __forceinline__ u64 fma2(u64 a, u64 b, u64 c) {
    u64 d; asm("fma.rn.f32x2 %0,%1,%2,%3;" : "=l"(d) : "l"(a), "l"(b), "l"(c));
    return d;
}
__device__ __forceinline__ u64 mul2(u64 a, u64 b) {
    u64 d; asm("mul.rn.f32x2 %0,%1,%2;" : "=l"(d) : "l"(a), "l"(b));
    return d;
}
__device__ __forceinline__ u64 dup2(float a) {
    u64 d; asm("mov.b64 %0,{%1,%1};" : "=l"(d) : "f"(a));
    return d;
}
__device__ __forceinline__ float2 unpk(u64 v) {
    float2 f; asm("mov.b64 {%0,%1},%2;" : "=f"(f.x), "=f"(f.y) : "l"(v));
    return f;
}

// Scratch for q, k, v projections: [B*T, H] each
__device__ float g_q[(size_t)B_ * T_ * H_];
__device__ float g_k[(size_t)B_ * T_ * H_];
__device__ float g_v[(size_t)B_ * T_ * H_];

// ---------------------------------------------------------------------------
// Kernel 1: fused QKV projection.  Y = X[16384,1024] @ W[1024,128]
// 128x128x16 tile, 256 threads, 8x8 microtile, f32x2 packed over N.
// ---------------------------------------------------------------------------
__global__ __launch_bounds__(256) void qkv_kernel(
    const float* __restrict__ x,
    const float* __restrict__ Wq,
    const float* __restrict__ Wk,
    const float* __restrict__ Wv)
{
    __shared__ float As[16][132];   // [k][m]
    __shared__ float Bs[16][132];   // [k][n]  (n contiguous -> free f32x2 pairs)

    const float* W  = (blockIdx.y == 0) ? Wq : (blockIdx.y == 1 ? Wk : Wv);
    float*      out = (blockIdx.y == 0) ? g_q : (blockIdx.y == 1 ? g_k : g_v);

    const int m0  = blockIdx.x * 128;
    const int tid = threadIdx.x;
    const int ty  = tid >> 4, tx = tid & 15;
    const int lr  = tid >> 2, lc = (tid & 3) * 4;
    const int wr  = tid >> 5, wc = (tid & 31) * 4;

    u64 acc2[8][4];
#pragma unroll
    for (int i = 0; i < 8; i++)
#pragma unroll
        for (int j = 0; j < 4; j++) acc2[i][j] = 0ULL;

    for (int k0 = 0; k0 < D_; k0 += 16) {
        float4 xa = *(const float4*)(x + (size_t)(m0 + lr)      * D_ + k0 + lc);
        float4 xb = *(const float4*)(x + (size_t)(m0 + lr + 64) * D_ + k0 + lc);
        float4 wa = *(const float4*)(W + (size_t)(k0 + wr)     * H_ + wc);
        float4 wb = *(const float4*)(W + (size_t)(k0 + wr + 8) * H_ + wc);
        __syncthreads();
        As[lc + 0][lr] = xa.x; As[lc + 1][lr] = xa.y;
        As[lc + 2][lr] = xa.z; As[lc + 3][lr] = xa.w;
        As[lc + 0][lr + 64] = xb.x; As[lc + 1][lr + 64] = xb.y;
        As[lc + 2][lr + 64] = xb.z; As[lc + 3][lr + 64] = xb.w;
        *(float4*)&Bs[wr][wc]     = wa;
        *(float4*)&Bs[wr + 8][wc] = wb;
        __syncthreads();
#pragma unroll
        for (int kk = 0; kk < 16; kk++) {
            float4 a0 = *(float4*)&As[kk][ty * 4];
            float4 a1 = *(float4*)&As[kk][64 + ty * 4];
            ulonglong2 b0 = *(ulonglong2*)&Bs[kk][tx * 4];
            ulonglong2 b1 = *(ulonglong2*)&Bs[kk][64 + tx * 4];
            float a[8] = {a0.x, a0.y, a0.z, a0.w, a1.x, a1.y, a1.z, a1.w};
#pragma unroll
            for (int i = 0; i < 8; i++) {
                u64 ad = dup2(a[i]);
                acc2[i][0] = fma2(ad, b0.x, acc2[i][0]);
                acc2[i][1] = fma2(ad, b0.y, acc2[i][1]);
                acc2[i][2] = fma2(ad, b1.x, acc2[i][2]);
                acc2[i][3] = fma2(ad, b1.y, acc2[i][3]);
            }
        }
    }

#pragma unroll
    for (int i = 0; i < 8; i++) {
        int row = m0 + ((i < 4) ? (ty * 4 + i) : (64 + ty * 4 + i - 4));
        float2 p0 = unpk(acc2[i][0]), p1 = unpk(acc2[i][1]);
        float2 p2 = unpk(acc2[i][2]), p3 = unpk(acc2[i][3]);
        float4 c0 = make_float4(p0.x, p0.y, p1.x, p1.y);
        float4 c1 = make_float4(p2.x, p2.y, p3.x, p3.y);
        *(float4*)(out + (size_t)row * H_ + tx * 4)      = c0;
        *(float4*)(out + (size_t)row * H_ + 64 + tx * 4) = c1;
    }
}

// ---------------------------------------------------------------------------
// Kernel 2: causal flash attention, fp32 f32x2, BQ = BK = 64.
// Q,K stored TRANSPOSED in smem as [kk][row], stride 68, with XOR swizzle of
// the column float4-group by sigma = (kk>>2)&7 -> conflict-free scalar
// transpose-stores AND conflict-free vector reads.
// grid (16, 8): block handles q-tiles x and 31-x -> exactly 33 k-tiles each.
// ---------------------------------------------------------------------------
#define KTS 68          // transposed row stride (floats); ==4 mod 8 required
#define VST 132
#define PST 65
#define SM_QT 0
#define SM_KT (128 * KTS)
#define SM_V  (2 * 128 * KTS)
#define SM_P  (SM_V + 64 * VST)
#define SM_M  (SM_P + 64 * PST)
#define SM_L  (SM_M + 64)
#define SM_C  (SM_L + 64)
#define SMEM_FLOATS (SM_C + 64)
#define SMEM_BYTES (SMEM_FLOATS * 4)

// transpose+swizzle store of one gmem float4 (row r, cols c..c+3) into T[kk][col]
__device__ __forceinline__ void store_trans(float* T, int r, int cg4, float4 v)
{
    const int sig   = cg4 & 7;
    const int colsw = (((r >> 2) ^ sig) << 2) | (r & 3);
    float* dst = T + (cg4 * 4) * KTS + colsw;
    dst[0 * KTS] = v.x; dst[1 * KTS] = v.y;
    dst[2 * KTS] = v.z; dst[3 * KTS] = v.w;
}

__global__ __launch_bounds__(256, 1) void attn_kernel(float* __restrict__ out)
{
    extern __shared__ float sm[];
    float* Qt  = sm + SM_QT;   // [128][KTS]  (kk-major, swizzled)
    float* Kt  = sm + SM_KT;   // [128][KTS]
    float* Vs  = sm + SM_V;    // [64][VST]   row-major
    float* Ps  = sm + SM_P;    // [64][PST]
    float* m_s = sm + SM_M;
    float* l_s = sm + SM_L;
    float* c_s = sm + SM_C;

    const int tid = threadIdx.x;
    const int b   = blockIdx.y;
    const int ty  = tid >> 4, tx = tid & 15;
    const int rg  = ty,       cg = tx;

    for (int pass = 0; pass < 2; pass++) {
        const int qt = pass ? (31 - (int)blockIdx.x) : (int)blockIdx.x;
        const size_t qbase = ((size_t)b * T_ + (size_t)qt * 64) * H_;

        __syncthreads();
        if (tid < 64) { m_s[tid] = -INFINITY; l_s[tid] = 0.f; }
        for (int i = tid; i < 64 * 32; i += 256) {
            int r = i >> 5, cg4 = i & 31;
            float4 v = *(const float4*)(g_q + qbase + (size_t)r * H_ + cg4 * 4);
            store_trans(Qt, r, cg4, v);
        }
        u64 o2[4][4];
#pragma unroll
        for (int i = 0; i < 4; i++)
#pragma unroll
            for (int j = 0; j < 4; j++) o2[i][j] = 0ULL;
        __syncthreads();

        for (int kt = 0; kt <= qt; kt++) {
            const size_t kbase = ((size_t)b * T_ + (size_t)kt * 64) * H_;
            for (int i = tid; i < 64 * 32; i += 256) {
                int r = i >> 5, cg4 = i & 31;
                float4 kv = *(const float4*)(g_k + kbase + (size_t)r * H_ + cg4 * 4);
                float4 vv = *(const float4*)(g_v + kbase + (size_t)r * H_ + cg4 * 4);
                store_trans(Kt, r, cg4, kv);
                *(float4*)&Vs[r * VST + cg4 * 4] = vv;
            }
            __syncthreads();

            // ---- S = Q K^T : 4 rows x (2 packed col-pairs) per thread ----
            u64 s2[4][2];
#pragma unroll
            for (int i = 0; i < 4; i++) { s2[i][0] = 0ULL; s2[i][1] = 0ULL; }

            for (int kb = 0; kb < 128; kb += 4) {
                const int sig = (kb >> 2) & 7;
                const float* qp = Qt + kb * KTS + ((ty ^ sig) << 2);
                const float* kp = Kt + kb * KTS + ((tx ^ sig) << 2);
#pragma unroll
                for (int kk2 = 0; kk2 < 4; kk2++) {
                    float4     qv = *(const float4*)(qp + kk2 * KTS);
                    ulonglong2 kv = *(const ulonglong2*)(kp + kk2 * KTS);
                    u64 q0 = dup2(qv.x), q1 = dup2(qv.y);
                    u64 q2 = dup2(qv.z), q3 = dup2(qv.w);
                    s2[0][0] = fma2(q0, kv.x, s2[0][0]);
                    s2[0][1] = fma2(q0, kv.y, s2[0][1]);
                    s2[1][0] = fma2(q1, kv.x, s2[1][0]);
                    s2[1][1] = fma2(q1, kv.y, s2[1][1]);
                    s2[2][0] = fma2(q2, kv.x, s2[2][0]);
                    s2[2][1] = fma2(q2, kv.y, s2[2][1]);
                    s2[3][0] = fma2(q3, kv.x, s2[3][0]);
                    s2[3][1] = fma2(q3, kv.y, s2[3][1]);
                }
            }

            // ---- online softmax (per row, 16-lane reductions) ----
#pragma unroll
            for (int i = 0; i < 4; i++) {
                const int r = ty * 4 + i;
                float2 sa = unpk(s2[i][0]);
                float2 sb = unpk(s2[i][1]);
                float sc[4] = {sa.x * SCALE, sa.y * SCALE,
                               sb.x * SCALE, sb.y * SCALE};
                float rm = -INFINITY;
#pragma unroll
                for (int j = 0; j < 4; j++) {
                    if (kt == qt && (tx * 4 + j) > r) sc[j] = -INFINITY;
                    rm = fmaxf(rm, sc[j]);
                }
#pragma unroll
                for (int d = 1; d < 16; d <<= 1)
                    rm = fmaxf(rm, __shfl_xor_sync(0xffffffffu, rm, d));
                const float mold = m_s[r];
                const float mnew = fmaxf(mold, rm);
                float rs = 0.f;
#pragma unroll
                for (int j = 0; j < 4; j++) {
                    float p = __expf(sc[j] - mnew);
                    Ps[r * PST + tx * 4 + j] = p;
                    rs += p;
                }
#pragma unroll
                for (int d = 1; d < 16; d <<= 1)
                    rs += __shfl_xor_sync(0xffffffffu, rs, d);
                if (tx == 0) {
                    float corr = __expf(mold - mnew);
                    c_s[r] = corr;
                    l_s[r] = l_s[r] * corr + rs;
                    m_s[r] = mnew;
                }
            }
            __syncthreads();

            // ---- O = O*corr + P @ V  (f32x2, 4 rows x 4 col-pairs) ----
#pragma unroll
            for (int i = 0; i < 4; i++) {
                u64 cr = dup2(c_s[rg * 4 + i]);
#pragma unroll
                for (int j = 0; j < 4; j++) o2[i][j] = mul2(o2[i][j], cr);
            }
            for (int j2 = 0; j2 < 64; j2++) {
                ulonglong2 va = *(ulonglong2*)&Vs[j2 * VST + cg * 4];
                ulonglong2 vb = *(ulonglong2*)&Vs[j2 * VST + 64 + cg * 4];
#pragma unroll
                for (int i = 0; i < 4; i++) {
                    u64 pd = dup2(Ps[(rg * 4 + i) * PST + j2]);
                    o2[i][0] = fma2(pd, va.x, o2[i][0]);
                    o2[i][1] = fma2(pd, va.y, o2[i][1]);
                    o2[i][2] = fma2(pd, vb.x, o2[i][2]);
                    o2[i][3] = fma2(pd, vb.y, o2[i][3]);
                }
            }
            __syncthreads();
        }

        // ---- epilogue: normalize and store ----
#pragma unroll
        for (int i = 0; i < 4; i++) {
            const int r = rg * 4 + i;
            const float inv = 1.f / l_s[r];
            float2 p0 = unpk(o2[i][0]), p1 = unpk(o2[i][1]);
            float2 p2 = unpk(o2[i][2]), p3 = unpk(o2[i][3]);
            float4 c0 = make_float4(p0.x * inv, p0.y * inv, p1.x * inv, p1.y * inv);
            float4 c1 = make_float4(p2.x * inv, p2.y * inv, p3.x * inv, p3.y * inv);
            float* dst = out + qbase + (size_t)r * H_;
            *(float4*)(dst + cg * 4)      = c0;
            *(float4*)(dst + 64 + cg * 4) = c1;
        }
    }
}

// ---------------------------------------------------------------------------
extern "C" void kernel_launch(void* const* d_in, const int* in_sizes, int n_in,
                              void* d_out, int out_size)
{
    const float* x  = (const float*)d_in[0];
    const float* Wq = (const float*)d_in[1];
    const float* Wk = (const float*)d_in[2];
    const float* Wv = (const float*)d_in[3];
    float* out = (float*)d_out;

    qkv_kernel<<<dim3(128, 3), 256>>>(x, Wq, Wk, Wv);

    cudaFuncSetAttribute(attn_kernel,
                         cudaFuncAttributeMaxDynamicSharedMemorySize,
                         SMEM_BYTES);
    attn_kernel<<<dim3(16, 8), 256, SMEM_BYTES>>>(out);
}

// round 4
// speedup vs baseline: 1.7596x; 1.2352x over previous
#include <cuda_runtime.h>
#include <cuda_bf16.h>
#include <math.h>
#include <stdint.h>

#define B_ 8
#define T_ 2048
#define D_ 1024
#define H_ 128
#define SCALE 0.08838834764831845f   // 1/sqrt(128)

typedef unsigned long long u64;

// ---- f32x2 packed helpers ----
__device__ __forceinline__ u64 fma2(u64 a, u64 b, u64 c) {
    u64 d; asm("fma.rn.f32x2 %0,%1,%2,%3;" : "=l"(d) : "l"(a), "l"(b), "l"(c));
    return d;
}
__device__ __forceinline__ u64 mul2(u64 a, u64 b) {
    u64 d; asm("mul.rn.f32x2 %0,%1,%2;" : "=l"(d) : "l"(a), "l"(b));
    return d;
}
__device__ __forceinline__ u64 dup2(float a) {
    u64 d; asm("mov.b64 %0,{%1,%1};" : "=l"(d) : "f"(a));
    return d;
}
__device__ __forceinline__ float2 unpk(u64 v) {
    float2 f; asm("mov.b64 {%0,%1},%2;" : "=f"(f.x), "=f"(f.y) : "l"(v));
    return f;
}

__device__ __forceinline__ uint32_t smem_u32(const void* p) {
    uint32_t a;
    asm("{ .reg .u64 t; cvta.to.shared.u64 t, %1; cvt.u32.u64 %0, t; }"
        : "=r"(a) : "l"(p));
    return a;
}
__device__ __forceinline__ uint32_t pack_bf(float a, float b) {
    __nv_bfloat162 t = __floats2bfloat162_rn(a, b);
    return *reinterpret_cast<uint32_t*>(&t);
}

#define LDSM4(r0, r1, r2, r3, addr) \
    asm volatile("ldmatrix.sync.aligned.m8n8.x4.shared.b16 {%0,%1,%2,%3}, [%4];" \
                 : "=r"(r0), "=r"(r1), "=r"(r2), "=r"(r3) : "r"(addr))

#define MMA16816(d, a, b) \
    asm volatile("mma.sync.aligned.m16n8k16.row.col.f32.bf16.bf16.f32 " \
                 "{%0,%1,%2,%3},{%4,%5,%6,%7},{%8,%9},{%0,%1,%2,%3};" \
                 : "+f"((d)[0]), "+f"((d)[1]), "+f"((d)[2]), "+f"((d)[3]) \
                 : "r"((a)[0]), "r"((a)[1]), "r"((a)[2]), "r"((a)[3]), \
                   "r"((b)[0]), "r"((b)[1]))

// ---- device scratch ----
__device__ float g_q[(size_t)B_ * T_ * H_];
__device__ float g_k[(size_t)B_ * T_ * H_];
__device__ float g_v[(size_t)B_ * T_ * H_];
__device__ __nv_bfloat16 g_Wb_hi[384 * 1024];   // Wcat[N=384][K=1024] K-major
__device__ __nv_bfloat16 g_Wb_lo[384 * 1024];

// ---------------------------------------------------------------------------
// Prep: Wcat[n][k] = W{q,k,v}[k][n%128] as bf16 hi + lo.
// ---------------------------------------------------------------------------
__global__ __launch_bounds__(256) void prep_w_kernel(
    const float* __restrict__ Wq,
    const float* __restrict__ Wk,
    const float* __restrict__ Wv)
{
    const int n = blockIdx.x;
    const float* W = (n < 128) ? Wq : (n < 256 ? Wk : Wv);
    const int h = n & 127;
    for (int k = threadIdx.x; k < 1024; k += 256) {
        float w = W[(size_t)k * H_ + h];
        __nv_bfloat16 hi = __float2bfloat16(w);
        float lo = w - __bfloat162float(hi);
        g_Wb_hi[(size_t)n * 1024 + k] = hi;
        g_Wb_lo[(size_t)n * 1024 + k] = __float2bfloat16(lo);
    }
}

// ---------------------------------------------------------------------------
// QKV GEMM via mma.sync bf16 split (hh + hl + lh).
// grid (128, 3): 128 M-tiles x {Wq,Wk,Wv}. CTA tile 128x128, 8 warps (2x4),
// warp tile 64x32. K chunk 64. SW128-swizzled smem, ldmatrix feeds frags.
// smem: A_hi 16K | A_lo 16K | B_hi 16K | B_lo 16K = 64KB dynamic.
// ---------------------------------------------------------------------------
#define AH_OFF 0
#define AL_OFF 16384
#define BH_OFF 32768
#define BL_OFF 49152
#define QK_SMEM 65536

__global__ __launch_bounds__(256, 1) void qkv_mma_kernel(const float* __restrict__ x)
{
    extern __shared__ char smq[];
    const uint32_t sb = smem_u32(smq);
    const int tid  = threadIdx.x;
    const int lane = tid & 31, warp = tid >> 5;
    const int wm = warp >> 2, wn = warp & 3;
    const int m0 = blockIdx.x * 128;
    const int n0 = blockIdx.y * 128;

    float acc[4][4][4];
#pragma unroll
    for (int mt = 0; mt < 4; mt++)
#pragma unroll
        for (int nt = 0; nt < 4; nt++)
#pragma unroll
            for (int j = 0; j < 4; j++) acc[mt][nt][j] = 0.f;

    // per-lane ldmatrix address components
    uint32_t a_rb[4], a_xr[4];
#pragma unroll
    for (int mt = 0; mt < 4; mt++) {
        int rowA = wm * 64 + mt * 16 + (lane & 15);
        a_rb[mt] = (uint32_t)(rowA * 128);
        a_xr[mt] = (uint32_t)((rowA & 7) << 4);
    }
    const uint32_t a_cb = (uint32_t)((lane >> 4) * 16);
    uint32_t b_rb[2], b_xr[2];
#pragma unroll
    for (int p = 0; p < 2; p++) {
        int nB = wn * 32 + p * 16 + ((lane >> 4) << 3) + (lane & 7);
        b_rb[p] = (uint32_t)(nB * 128);
        b_xr[p] = (uint32_t)((nB & 7) << 4);
    }
    const uint32_t b_cb = (uint32_t)(((lane >> 3) & 1) * 16);

    for (int kc = 0; kc < 16; kc++) {
        const int k0 = kc * 64;

        // ---- A tile: X[128,64] fp32 -> bf16 hi/lo, swizzled ----
#pragma unroll
        for (int i = 0; i < 8; i++) {
            int idx = i * 256 + tid;
            int r = idx >> 4, c4 = idx & 15;
            float4 f = *(const float4*)(x + (size_t)(m0 + r) * D_ + k0 + c4 * 4);
            __nv_bfloat16 h0 = __float2bfloat16(f.x);
            __nv_bfloat16 h1 = __float2bfloat16(f.y);
            __nv_bfloat16 h2 = __float2bfloat16(f.z);
            __nv_bfloat16 h3 = __float2bfloat16(f.w);
            uint2 hv, lv;
            hv.x = (uint32_t)__bfloat16_as_ushort(h0) |
                   ((uint32_t)__bfloat16_as_ushort(h1) << 16);
            hv.y = (uint32_t)__bfloat16_as_ushort(h2) |
                   ((uint32_t)__bfloat16_as_ushort(h3) << 16);
            lv.x = pack_bf(f.x - __bfloat162float(h0), f.y - __bfloat162float(h1));
            lv.y = pack_bf(f.z - __bfloat162float(h2), f.w - __bfloat162float(h3));
            uint32_t off = (uint32_t)(r * 128 + c4 * 8);
            uint32_t sw = off ^ ((off >> 3) & 0x70);
            *(uint2*)(smq + AH_OFF + sw) = hv;
            *(uint2*)(smq + AL_OFF + sw) = lv;
        }
        // ---- B tile: Wcat[128,64] bf16 hi/lo, swizzled ----
#pragma unroll
        for (int i = 0; i < 4; i++) {
            int idx = i * 256 + tid;
            int r = idx >> 3, c8 = idx & 7;
            uint32_t off = (uint32_t)(r * 128 + c8 * 16);
            uint32_t sw = off ^ ((off >> 3) & 0x70);
            const size_t ge = (size_t)(n0 + r) * 1024 + k0 + c8 * 8;
            *(float4*)(smq + BH_OFF + sw) = *(const float4*)(g_Wb_hi + ge);
            *(float4*)(smq + BL_OFF + sw) = *(const float4*)(g_Wb_lo + ge);
        }
        __syncthreads();

#pragma unroll
        for (int ks = 0; ks < 4; ks++) {
            const uint32_t acol = (a_cb + ks * 32);
            const uint32_t bcol = (b_cb + ks * 32);
            uint32_t ah[4][4], al[4][4];
#pragma unroll
            for (int mt = 0; mt < 4; mt++) {
                uint32_t adh = sb + AH_OFF + a_rb[mt] + (acol ^ a_xr[mt]);
                LDSM4(ah[mt][0], ah[mt][1], ah[mt][2], ah[mt][3], adh);
                uint32_t adl = sb + AL_OFF + a_rb[mt] + (acol ^ a_xr[mt]);
                LDSM4(al[mt][0], al[mt][1], al[mt][2], al[mt][3], adl);
            }
            uint32_t bh[4][2], bl[4][2];
#pragma unroll
            for (int p = 0; p < 2; p++) {
                uint32_t r0, r1, r2, r3;
                uint32_t bdh = sb + BH_OFF + b_rb[p] + (bcol ^ b_xr[p]);
                LDSM4(r0, r1, r2, r3, bdh);
                bh[2 * p][0] = r0; bh[2 * p][1] = r1;
                bh[2 * p + 1][0] = r2; bh[2 * p + 1][1] = r3;
                uint32_t bdl = sb + BL_OFF + b_rb[p] + (bcol ^ b_xr[p]);
                LDSM4(r0, r1, r2, r3, bdl);
                bl[2 * p][0] = r0; bl[2 * p][1] = r1;
                bl[2 * p + 1][0] = r2; bl[2 * p + 1][1] = r3;
            }
#pragma unroll
            for (int mt = 0; mt < 4; mt++)
#pragma unroll
                for (int nt = 0; nt < 4; nt++) {
                    MMA16816(acc[mt][nt], ah[mt], bh[nt]);
                    MMA16816(acc[mt][nt], ah[mt], bl[nt]);
                    MMA16816(acc[mt][nt], al[mt], bh[nt]);
                }
        }
        __syncthreads();
    }

    // ---- epilogue ----
    float* outp = (blockIdx.y == 0) ? g_q : (blockIdx.y == 1 ? g_k : g_v);
    const int g = lane >> 2, tig = lane & 3;
#pragma unroll
    for (int mt = 0; mt < 4; mt++) {
        const int row0 = m0 + wm * 64 + mt * 16 + g;
#pragma unroll
        for (int nt = 0; nt < 4; nt++) {
            const int col = wn * 32 + nt * 8 + tig * 2;
            *(float2*)(outp + (size_t)row0 * H_ + col) =
                make_float2(acc[mt][nt][0], acc[mt][nt][1]);
            *(float2*)(outp + (size_t)(row0 + 8) * H_ + col) =
                make_float2(acc[mt][nt][2], acc[mt][nt][3]);
        }
    }
}

// ---------------------------------------------------------------------------
// Kernel 2: causal flash attention, fp32 f32x2, BQ = BK = 64. (R2, unchanged)
// ---------------------------------------------------------------------------
#define KTS 68
#define VST 132
#define PST 65
#define SM_QT 0
#define SM_KT (128 * KTS)
#define SM_V  (2 * 128 * KTS)
#define SM_P  (SM_V + 64 * VST)
#define SM_M  (SM_P + 64 * PST)
#define SM_L  (SM_M + 64)
#define SM_C  (SM_L + 64)
#define SMEM_FLOATS (SM_C + 64)
#define SMEM_BYTES (SMEM_FLOATS * 4)

__device__ __forceinline__ void store_trans(float* T, int r, int cg4, float4 v)
{
    const int sig   = cg4 & 7;
    const int colsw = (((r >> 2) ^ sig) << 2) | (r & 3);
    float* dst = T + (cg4 * 4) * KTS + colsw;
    dst[0 * KTS] = v.x; dst[1 * KTS] = v.y;
    dst[2 * KTS] = v.z; dst[3 * KTS] = v.w;
}

__global__ __launch_bounds__(256, 1) void attn_kernel(float* __restrict__ out)
{
    extern __shared__ float sm[];
    float* Qt  = sm + SM_QT;
    float* Kt  = sm + SM_KT;
    float* Vs  = sm + SM_V;
    float* Ps  = sm + SM_P;
    float* m_s = sm + SM_M;
    float* l_s = sm + SM_L;
    float* c_s = sm + SM_C;

    const int tid = threadIdx.x;
    const int b   = blockIdx.y;
    const int ty  = tid >> 4, tx = tid & 15;
    const int rg  = ty,       cg = tx;

    for (int pass = 0; pass < 2; pass++) {
        const int qt = pass ? (31 - (int)blockIdx.x) : (int)blockIdx.x;
        const size_t qbase = ((size_t)b * T_ + (size_t)qt * 64) * H_;

        __syncthreads();
        if (tid < 64) { m_s[tid] = -INFINITY; l_s[tid] = 0.f; }
        for (int i = tid; i < 64 * 32; i += 256) {
            int r = i >> 5, cg4 = i & 31;
            float4 v = *(const float4*)(g_q + qbase + (size_t)r * H_ + cg4 * 4);
            store_trans(Qt, r, cg4, v);
        }
        u64 o2[4][4];
#pragma unroll
        for (int i = 0; i < 4; i++)
#pragma unroll
            for (int j = 0; j < 4; j++) o2[i][j] = 0ULL;
        __syncthreads();

        for (int kt = 0; kt <= qt; kt++) {
            const size_t kbase = ((size_t)b * T_ + (size_t)kt * 64) * H_;
            for (int i = tid; i < 64 * 32; i += 256) {
                int r = i >> 5, cg4 = i & 31;
                float4 kv = *(const float4*)(g_k + kbase + (size_t)r * H_ + cg4 * 4);
                float4 vv = *(const float4*)(g_v + kbase + (size_t)r * H_ + cg4 * 4);
                store_trans(Kt, r, cg4, kv);
                *(float4*)&Vs[r * VST + cg4 * 4] = vv;
            }
            __syncthreads();

            u64 s2[4][2];
#pragma unroll
            for (int i = 0; i < 4; i++) { s2[i][0] = 0ULL; s2[i][1] = 0ULL; }

            for (int kb = 0; kb < 128; kb += 4) {
                const int sig = (kb >> 2) & 7;
                const float* qp = Qt + kb * KTS + ((ty ^ sig) << 2);
                const float* kp = Kt + kb * KTS + ((tx ^ sig) << 2);
#pragma unroll
                for (int kk2 = 0; kk2 < 4; kk2++) {
                    float4     qv = *(const float4*)(qp + kk2 * KTS);
                    ulonglong2 kv = *(const ulonglong2*)(kp + kk2 * KTS);
                    u64 q0 = dup2(qv.x), q1 = dup2(qv.y);
                    u64 q2 = dup2(qv.z), q3 = dup2(qv.w);
                    s2[0][0] = fma2(q0, kv.x, s2[0][0]);
                    s2[0][1] = fma2(q0, kv.y, s2[0][1]);
                    s2[1][0] = fma2(q1, kv.x, s2[1][0]);
                    s2[1][1] = fma2(q1, kv.y, s2[1][1]);
                    s2[2][0] = fma2(q2, kv.x, s2[2][0]);
                    s2[2][1] = fma2(q2, kv.y, s2[2][1]);
                    s2[3][0] = fma2(q3, kv.x, s2[3][0]);
                    s2[3][1] = fma2(q3, kv.y, s2[3][1]);
                }
            }

#pragma unroll
            for (int i = 0; i < 4; i++) {
                const int r = ty * 4 + i;
                float2 sa  = unpk(s2[i][0]);
                float2 sb2 = unpk(s2[i][1]);
                float sc[4] = {sa.x * SCALE, sa.y * SCALE,
                               sb2.x * SCALE, sb2.y * SCALE};
                float rm = -INFINITY;
#pragma unroll
                for (int j = 0; j < 4; j++) {
                    if (kt == qt && (tx * 4 + j) > r) sc[j] = -INFINITY;
                    rm = fmaxf(rm, sc[j]);
                }
#pragma unroll
                for (int d = 1; d < 16; d <<= 1)
                    rm = fmaxf(rm, __shfl_xor_sync(0xffffffffu, rm, d));
                const float mold = m_s[r];
                const float mnew = fmaxf(mold, rm);
                float rs = 0.f;
#pragma unroll
                for (int j = 0; j < 4; j++) {
                    float p = __expf(sc[j] - mnew);
                    Ps[r * PST + tx * 4 + j] = p;
                    rs += p;
                }
#pragma unroll
                for (int d = 1; d < 16; d <<= 1)
                    rs += __shfl_xor_sync(0xffffffffu, rs, d);
                if (tx == 0) {
                    float corr = __expf(mold - mnew);
                    c_s[r] = corr;
                    l_s[r] = l_s[r] * corr + rs;
                    m_s[r] = mnew;
                }
            }
            __syncthreads();

#pragma unroll
            for (int i = 0; i < 4; i++) {
                u64 cr = dup2(c_s[rg * 4 + i]);
#pragma unroll
                for (int j = 0; j < 4; j++) o2[i][j] = mul2(o2[i][j], cr);
            }
            for (int j2 = 0; j2 < 64; j2++) {
                ulonglong2 va = *(ulonglong2*)&Vs[j2 * VST + cg * 4];
                ulonglong2 vb = *(ulonglong2*)&Vs[j2 * VST + 64 + cg * 4];
#pragma unroll
                for (int i = 0; i < 4; i++) {
                    u64 pd = dup2(Ps[(rg * 4 + i) * PST + j2]);
                    o2[i][0] = fma2(pd, va.x, o2[i][0]);
                    o2[i][1] = fma2(pd, va.y, o2[i][1]);
                    o2[i][2] = fma2(pd, vb.x, o2[i][2]);
                    o2[i][3] = fma2(pd, vb.y, o2[i][3]);
                }
            }
            __syncthreads();
        }

#pragma unroll
        for (int i = 0; i < 4; i++) {
            const int r = rg * 4 + i;
            const float inv = 1.f / l_s[r];
            float2 p0 = unpk(o2[i][0]), p1 = unpk(o2[i][1]);
            float2 p2 = unpk(o2[i][2]), p3 = unpk(o2[i][3]);
            float4 c0 = make_float4(p0.x * inv, p0.y * inv, p1.x * inv, p1.y * inv);
            float4 c1 = make_float4(p2.x * inv, p2.y * inv, p3.x * inv, p3.y * inv);
            float* dst = out + qbase + (size_t)r * H_;
            *(float4*)(dst + cg * 4)      = c0;
            *(float4*)(dst + 64 + cg * 4) = c1;
        }
    }
}

// ---------------------------------------------------------------------------
extern "C" void kernel_launch(void* const* d_in, const int* in_sizes, int n_in,
                              void* d_out, int out_size)
{
    const float* x  = (const float*)d_in[0];
    const float* Wq = (const float*)d_in[1];
    const float* Wk = (const float*)d_in[2];
    const float* Wv = (const float*)d_in[3];
    float* out = (float*)d_out;

    prep_w_kernel<<<384, 256>>>(Wq, Wk, Wv);

    cudaFuncSetAttribute(qkv_mma_kernel,
                         cudaFuncAttributeMaxDynamicSharedMemorySize, QK_SMEM);
    qkv_mma_kernel<<<dim3(128, 3), 256, QK_SMEM>>>(x);

    cudaFuncSetAttribute(attn_kernel,
                         cudaFuncAttributeMaxDynamicSharedMemorySize, SMEM_BYTES);
    attn_kernel<<<dim3(16, 8), 256, SMEM_BYTES>>>(out);
}

// round 5
// speedup vs baseline: 2.7923x; 1.5868x over previous
#include <cuda_runtime.h>
#include <cuda_bf16.h>
#include <math.h>
#include <stdint.h>

#define B_ 8
#define T_ 2048
#define D_ 1024
#define H_ 128
#define SCALE 0.08838834764831845f   // 1/sqrt(128)

__device__ __forceinline__ uint32_t smem_u32(const void* p) {
    uint32_t a;
    asm("{ .reg .u64 t; cvta.to.shared.u64 t, %1; cvt.u32.u64 %0, t; }"
        : "=r"(a) : "l"(p));
    return a;
}
__device__ __forceinline__ uint32_t pack_bf(float a, float b) {
    __nv_bfloat162 t = __floats2bfloat162_rn(a, b);
    return *reinterpret_cast<uint32_t*>(&t);
}

#define LDSM4(r0, r1, r2, r3, addr) \
    asm volatile("ldmatrix.sync.aligned.m8n8.x4.shared.b16 {%0,%1,%2,%3}, [%4];" \
                 : "=r"(r0), "=r"(r1), "=r"(r2), "=r"(r3) : "r"(addr))
#define LDSM4T(r0, r1, r2, r3, addr) \
    asm volatile("ldmatrix.sync.aligned.m8n8.x4.trans.shared.b16 {%0,%1,%2,%3}, [%4];" \
                 : "=r"(r0), "=r"(r1), "=r"(r2), "=r"(r3) : "r"(addr))

#define MMA16816(d, a, b) \
    asm volatile("mma.sync.aligned.m16n8k16.row.col.f32.bf16.bf16.f32 " \
                 "{%0,%1,%2,%3},{%4,%5,%6,%7},{%8,%9},{%0,%1,%2,%3};" \
                 : "+f"((d)[0]), "+f"((d)[1]), "+f"((d)[2]), "+f"((d)[3]) \
                 : "r"((a)[0]), "r"((a)[1]), "r"((a)[2]), "r"((a)[3]), \
                   "r"((b)[0]), "r"((b)[1]))

// ---- device scratch: projections stored as bf16 hi/lo ----
__device__ __nv_bfloat16 g_q_hi[(size_t)B_ * T_ * H_];
__device__ __nv_bfloat16 g_q_lo[(size_t)B_ * T_ * H_];
__device__ __nv_bfloat16 g_k_hi[(size_t)B_ * T_ * H_];
__device__ __nv_bfloat16 g_k_lo[(size_t)B_ * T_ * H_];
__device__ __nv_bfloat16 g_v_hi[(size_t)B_ * T_ * H_];
__device__ __nv_bfloat16 g_v_lo[(size_t)B_ * T_ * H_];
__device__ __nv_bfloat16 g_Wb_hi[384 * 1024];
__device__ __nv_bfloat16 g_Wb_lo[384 * 1024];

// ---------------------------------------------------------------------------
// Prep: Wcat[n][k] = W{q,k,v}[k][n%128] as bf16 hi + lo.
// ---------------------------------------------------------------------------
__global__ __launch_bounds__(256) void prep_w_kernel(
    const float* __restrict__ Wq,
    const float* __restrict__ Wk,
    const float* __restrict__ Wv)
{
    const int n = blockIdx.x;
    const float* W = (n < 128) ? Wq : (n < 256 ? Wk : Wv);
    const int h = n & 127;
    for (int k = threadIdx.x; k < 1024; k += 256) {
        float w = W[(size_t)k * H_ + h];
        __nv_bfloat16 hi = __float2bfloat16(w);
        float lo = w - __bfloat162float(hi);
        g_Wb_hi[(size_t)n * 1024 + k] = hi;
        g_Wb_lo[(size_t)n * 1024 + k] = __float2bfloat16(lo);
    }
}

// ---------------------------------------------------------------------------
// QKV GEMM via mma.sync bf16 split. Epilogue emits bf16 hi/lo.
// ---------------------------------------------------------------------------
#define AH_OFF 0
#define AL_OFF 16384
#define BH_OFF 32768
#define BL_OFF 49152
#define QK_SMEM 65536

__global__ __launch_bounds__(256, 1) void qkv_mma_kernel(const float* __restrict__ x)
{
    extern __shared__ char smq[];
    const uint32_t sb = smem_u32(smq);
    const int tid  = threadIdx.x;
    const int lane = tid & 31, warp = tid >> 5;
    const int wm = warp >> 2, wn = warp & 3;
    const int m0 = blockIdx.x * 128;
    const int n0 = blockIdx.y * 128;

    float acc[4][4][4];
#pragma unroll
    for (int mt = 0; mt < 4; mt++)
#pragma unroll
        for (int nt = 0; nt < 4; nt++)
#pragma unroll
            for (int j = 0; j < 4; j++) acc[mt][nt][j] = 0.f;

    uint32_t a_rb[4], a_xr[4];
#pragma unroll
    for (int mt = 0; mt < 4; mt++) {
        int rowA = wm * 64 + mt * 16 + (lane & 15);
        a_rb[mt] = (uint32_t)(rowA * 128);
        a_xr[mt] = (uint32_t)((rowA & 7) << 4);
    }
    const uint32_t a_cb = (uint32_t)((lane >> 4) * 16);
    uint32_t b_rb[2], b_xr[2];
#pragma unroll
    for (int p = 0; p < 2; p++) {
        int nB = wn * 32 + p * 16 + ((lane >> 4) << 3) + (lane & 7);
        b_rb[p] = (uint32_t)(nB * 128);
        b_xr[p] = (uint32_t)((nB & 7) << 4);
    }
    const uint32_t b_cb = (uint32_t)(((lane >> 3) & 1) * 16);

    for (int kc = 0; kc < 16; kc++) {
        const int k0 = kc * 64;
#pragma unroll
        for (int i = 0; i < 8; i++) {
            int idx = i * 256 + tid;
            int r = idx >> 4, c4 = idx & 15;
            float4 f = *(const float4*)(x + (size_t)(m0 + r) * D_ + k0 + c4 * 4);
            __nv_bfloat16 h0 = __float2bfloat16(f.x);
            __nv_bfloat16 h1 = __float2bfloat16(f.y);
            __nv_bfloat16 h2 = __float2bfloat16(f.z);
            __nv_bfloat16 h3 = __float2bfloat16(f.w);
            uint2 hv, lv;
            hv.x = (uint32_t)__bfloat16_as_ushort(h0) |
                   ((uint32_t)__bfloat16_as_ushort(h1) << 16);
            hv.y = (uint32_t)__bfloat16_as_ushort(h2) |
                   ((uint32_t)__bfloat16_as_ushort(h3) << 16);
            lv.x = pack_bf(f.x - __bfloat162float(h0), f.y - __bfloat162float(h1));
            lv.y = pack_bf(f.z - __bfloat162float(h2), f.w - __bfloat162float(h3));
            uint32_t off = (uint32_t)(r * 128 + c4 * 8);
            uint32_t sw = off ^ ((off >> 3) & 0x70);
            *(uint2*)(smq + AH_OFF + sw) = hv;
            *(uint2*)(smq + AL_OFF + sw) = lv;
        }
#pragma unroll
        for (int i = 0; i < 4; i++) {
            int idx = i * 256 + tid;
            int r = idx >> 3, c8 = idx & 7;
            uint32_t off = (uint32_t)(r * 128 + c8 * 16);
            uint32_t sw = off ^ ((off >> 3) & 0x70);
            const size_t ge = (size_t)(n0 + r) * 1024 + k0 + c8 * 8;
            *(float4*)(smq + BH_OFF + sw) = *(const float4*)(g_Wb_hi + ge);
            *(float4*)(smq + BL_OFF + sw) = *(const float4*)(g_Wb_lo + ge);
        }
        __syncthreads();

#pragma unroll
        for (int ks = 0; ks < 4; ks++) {
            const uint32_t acol = (a_cb + ks * 32);
            const uint32_t bcol = (b_cb + ks * 32);
            uint32_t ah[4][4], al[4][4];
#pragma unroll
            for (int mt = 0; mt < 4; mt++) {
                LDSM4(ah[mt][0], ah[mt][1], ah[mt][2], ah[mt][3],
                      sb + AH_OFF + a_rb[mt] + (acol ^ a_xr[mt]));
                LDSM4(al[mt][0], al[mt][1], al[mt][2], al[mt][3],
                      sb + AL_OFF + a_rb[mt] + (acol ^ a_xr[mt]));
            }
            uint32_t bh[4][2], bl[4][2];
#pragma unroll
            for (int p = 0; p < 2; p++) {
                uint32_t r0, r1, r2, r3;
                LDSM4(r0, r1, r2, r3, sb + BH_OFF + b_rb[p] + (bcol ^ b_xr[p]));
                bh[2 * p][0] = r0; bh[2 * p][1] = r1;
                bh[2 * p + 1][0] = r2; bh[2 * p + 1][1] = r3;
                LDSM4(r0, r1, r2, r3, sb + BL_OFF + b_rb[p] + (bcol ^ b_xr[p]));
                bl[2 * p][0] = r0; bl[2 * p][1] = r1;
                bl[2 * p + 1][0] = r2; bl[2 * p + 1][1] = r3;
            }
#pragma unroll
            for (int mt = 0; mt < 4; mt++)
#pragma unroll
                for (int nt = 0; nt < 4; nt++) {
                    MMA16816(acc[mt][nt], ah[mt], bh[nt]);
                    MMA16816(acc[mt][nt], ah[mt], bl[nt]);
                    MMA16816(acc[mt][nt], al[mt], bh[nt]);
                }
        }
        __syncthreads();
    }

    // ---- epilogue: fp32 acc -> bf16 hi/lo arrays ----
    __nv_bfloat16* oh = (blockIdx.y == 0) ? g_q_hi : (blockIdx.y == 1 ? g_k_hi : g_v_hi);
    __nv_bfloat16* ol = (blockIdx.y == 0) ? g_q_lo : (blockIdx.y == 1 ? g_k_lo : g_v_lo);
    const int g = lane >> 2, tig = lane & 3;
#pragma unroll
    for (int mt = 0; mt < 4; mt++) {
        const int row0 = m0 + wm * 64 + mt * 16 + g;
#pragma unroll
        for (int nt = 0; nt < 4; nt++) {
            const int col = wn * 32 + nt * 8 + tig * 2;
#pragma unroll
            for (int h = 0; h < 2; h++) {
                const int row = row0 + h * 8;
                float a0 = acc[mt][nt][2 * h], a1 = acc[mt][nt][2 * h + 1];
                __nv_bfloat16 h0 = __float2bfloat16(a0);
                __nv_bfloat16 h1 = __float2bfloat16(a1);
                *(uint32_t*)(oh + (size_t)row * H_ + col) =
                    (uint32_t)__bfloat16_as_ushort(h0) |
                    ((uint32_t)__bfloat16_as_ushort(h1) << 16);
                *(uint32_t*)(ol + (size_t)row * H_ + col) =
                    pack_bf(a0 - __bfloat162float(h0), a1 - __bfloat162float(h1));
            }
        }
    }
}

// ---------------------------------------------------------------------------
// Flash attention via mma.sync bf16 split. BQ=BK=64, 256 thr, warps 2x4.
// grid (16, 8): block does q-tiles x and 31-x (33 k-tiles, balanced).
// ---------------------------------------------------------------------------
#define AQH 0
#define AQL 16384
#define AKH 32768
#define AKL 49152
#define AVH 65536
#define AVL 81920
#define ASS 98304                    // 64 x 68 fp32
#define APH (ASS + 64 * 68 * 4)      // 115712
#define APL (APH + 8192)             // 123904
#define AMS (APL + 8192)             // 132096
#define ALS (AMS + 256)
#define ACS (ALS + 256)
#define ATT_SMEM (ACS + 256)         // 132864

__global__ __launch_bounds__(256, 1) void attn_mma_kernel(float* __restrict__ out)
{
    extern __shared__ char smA[];
    const uint32_t sb = smem_u32(smA);
    float* Ss  = (float*)(smA + ASS);
    float* m_s = (float*)(smA + AMS);
    float* l_s = (float*)(smA + ALS);
    float* c_s = (float*)(smA + ACS);

    const int tid  = threadIdx.x;
    const int lane = tid & 31, warp = tid >> 5;
    const int wm = warp >> 2, wn = warp & 3;
    const int b  = blockIdx.y;
    const int ty = tid >> 4, tx = tid & 15;
    const int g4 = lane >> 2, tig = lane & 3;

    for (int pass = 0; pass < 2; pass++) {
        const int qt = pass ? (31 - (int)blockIdx.x) : (int)blockIdx.x;
        const size_t qbase = ((size_t)b * T_ + (size_t)qt * 64) * H_;

        __syncthreads();
        if (tid < 64) { m_s[tid] = -INFINITY; l_s[tid] = 0.f; }
        // load Q hi/lo: 64 rows x 16 granules(16B)
#pragma unroll
        for (int i = 0; i < 4; i++) {
            int idx = i * 256 + tid;
            int r = idx >> 4, gq = idx & 15;
            uint32_t off = (uint32_t)(r * 256 + ((gq ^ (r & 7)) << 4));
            *(uint4*)(smA + AQH + off) = *(const uint4*)(g_q_hi + qbase + r * 128 + gq * 8);
            *(uint4*)(smA + AQL + off) = *(const uint4*)(g_q_lo + qbase + r * 128 + gq * 8);
        }
        float oacc[2][4][4];
#pragma unroll
        for (int mt = 0; mt < 2; mt++)
#pragma unroll
            for (int nv = 0; nv < 4; nv++)
#pragma unroll
                for (int j = 0; j < 4; j++) oacc[mt][nv][j] = 0.f;
        __syncthreads();

        for (int kt = 0; kt <= qt; kt++) {
            const size_t kbase = ((size_t)b * T_ + (size_t)kt * 64) * H_;
#pragma unroll
            for (int i = 0; i < 4; i++) {
                int idx = i * 256 + tid;
                int r = idx >> 4, gq = idx & 15;
                uint32_t off = (uint32_t)(r * 256 + ((gq ^ (r & 7)) << 4));
                const size_t ge = kbase + r * 128 + gq * 8;
                *(uint4*)(smA + AKH + off) = *(const uint4*)(g_k_hi + ge);
                *(uint4*)(smA + AKL + off) = *(const uint4*)(g_k_lo + ge);
                *(uint4*)(smA + AVH + off) = *(const uint4*)(g_v_hi + ge);
                *(uint4*)(smA + AVL + off) = *(const uint4*)(g_v_lo + ge);
            }
            __syncthreads();

            // ---- S = Q K^T (3-term bf16 split) ----
            float sacc[2][2][4];
#pragma unroll
            for (int mt = 0; mt < 2; mt++)
#pragma unroll
                for (int nt = 0; nt < 2; nt++)
#pragma unroll
                    for (int j = 0; j < 4; j++) sacc[mt][nt][j] = 0.f;

#pragma unroll
            for (int ks = 0; ks < 8; ks++) {
                uint32_t ah[2][4], al[2][4];
#pragma unroll
                for (int mt = 0; mt < 2; mt++) {
                    int r = wm * 32 + mt * 16 + (lane & 15);
                    int gq = ks * 2 + (lane >> 4);
                    uint32_t off = (uint32_t)(r * 256 + ((gq ^ (r & 7)) << 4));
                    LDSM4(ah[mt][0], ah[mt][1], ah[mt][2], ah[mt][3], sb + AQH + off);
                    LDSM4(al[mt][0], al[mt][1], al[mt][2], al[mt][3], sb + AQL + off);
                }
                uint32_t bh[2][2], bl[2][2];
                {
                    int r = wn * 16 + ((lane >> 4) << 3) + (lane & 7);
                    int gq = ks * 2 + ((lane >> 3) & 1);
                    uint32_t off = (uint32_t)(r * 256 + ((gq ^ (r & 7)) << 4));
                    uint32_t r0, r1, r2, r3;
                    LDSM4(r0, r1, r2, r3, sb + AKH + off);
                    bh[0][0] = r0; bh[0][1] = r1; bh[1][0] = r2; bh[1][1] = r3;
                    LDSM4(r0, r1, r2, r3, sb + AKL + off);
                    bl[0][0] = r0; bl[0][1] = r1; bl[1][0] = r2; bl[1][1] = r3;
                }
#pragma unroll
                for (int mt = 0; mt < 2; mt++)
#pragma unroll
                    for (int nt = 0; nt < 2; nt++) {
                        MMA16816(sacc[mt][nt], ah[mt], bh[nt]);
                        MMA16816(sacc[mt][nt], ah[mt], bl[nt]);
                        MMA16816(sacc[mt][nt], al[mt], bh[nt]);
                    }
            }
            // store S to smem
#pragma unroll
            for (int mt = 0; mt < 2; mt++)
#pragma unroll
                for (int nt = 0; nt < 2; nt++) {
                    int r = wm * 32 + mt * 16 + g4;
                    int c = wn * 16 + nt * 8 + tig * 2;
                    *(float2*)&Ss[r * 68 + c] =
                        make_float2(sacc[mt][nt][0], sacc[mt][nt][1]);
                    *(float2*)&Ss[(r + 8) * 68 + c] =
                        make_float2(sacc[mt][nt][2], sacc[mt][nt][3]);
                }
            __syncthreads();

            // ---- softmax (half-warp per row-group) ----
#pragma unroll
            for (int i = 0; i < 4; i++) {
                const int r = ty * 4 + i;
                float4 sv = *(float4*)&Ss[r * 68 + tx * 4];
                float sc[4] = {sv.x * SCALE, sv.y * SCALE, sv.z * SCALE, sv.w * SCALE};
                float rm = -INFINITY;
#pragma unroll
                for (int j = 0; j < 4; j++) {
                    if (kt == qt && (tx * 4 + j) > r) sc[j] = -INFINITY;
                    rm = fmaxf(rm, sc[j]);
                }
#pragma unroll
                for (int d = 1; d < 16; d <<= 1)
                    rm = fmaxf(rm, __shfl_xor_sync(0xffffffffu, rm, d));
                const float mold = m_s[r];
                const float mnew = fmaxf(mold, rm);
                float p[4], rs = 0.f;
#pragma unroll
                for (int j = 0; j < 4; j++) { p[j] = __expf(sc[j] - mnew); rs += p[j]; }
                // pack P hi/lo (4 bf16 = 8B) into swizzled smem
                __nv_bfloat16 ph0 = __float2bfloat16(p[0]);
                __nv_bfloat16 ph1 = __float2bfloat16(p[1]);
                __nv_bfloat16 ph2 = __float2bfloat16(p[2]);
                __nv_bfloat16 ph3 = __float2bfloat16(p[3]);
                uint2 hv, lv;
                hv.x = (uint32_t)__bfloat16_as_ushort(ph0) |
                       ((uint32_t)__bfloat16_as_ushort(ph1) << 16);
                hv.y = (uint32_t)__bfloat16_as_ushort(ph2) |
                       ((uint32_t)__bfloat16_as_ushort(ph3) << 16);
                lv.x = pack_bf(p[0] - __bfloat162float(ph0), p[1] - __bfloat162float(ph1));
                lv.y = pack_bf(p[2] - __bfloat162float(ph2), p[3] - __bfloat162float(ph3));
                uint32_t off = (uint32_t)(r * 128 + (((tx >> 1) ^ (r & 7)) << 4) + (tx & 1) * 8);
                *(uint2*)(smA + APH + off) = hv;
                *(uint2*)(smA + APL + off) = lv;
#pragma unroll
                for (int d = 1; d < 16; d <<= 1)
                    rs += __shfl_xor_sync(0xffffffffu, rs, d);
                if (tx == 0) {
                    float corr = __expf(mold - mnew);
                    c_s[r] = corr;
                    l_s[r] = l_s[r] * corr + rs;
                    m_s[r] = mnew;
                }
            }
            __syncthreads();

            // ---- O *= corr ; O += P V (3-term) ----
#pragma unroll
            for (int mt = 0; mt < 2; mt++) {
                const int r0 = wm * 32 + mt * 16 + g4;
                float c0 = c_s[r0], c1 = c_s[r0 + 8];
#pragma unroll
                for (int nv = 0; nv < 4; nv++) {
                    oacc[mt][nv][0] *= c0; oacc[mt][nv][1] *= c0;
                    oacc[mt][nv][2] *= c1; oacc[mt][nv][3] *= c1;
                }
            }
#pragma unroll
            for (int ks = 0; ks < 4; ks++) {
                uint32_t aph[2][4], apl[2][4];
#pragma unroll
                for (int mt = 0; mt < 2; mt++) {
                    int r = wm * 32 + mt * 16 + (lane & 15);
                    int gq = ks * 2 + (lane >> 4);
                    uint32_t off = (uint32_t)(r * 128 + ((gq ^ (r & 7)) << 4));
                    LDSM4(aph[mt][0], aph[mt][1], aph[mt][2], aph[mt][3], sb + APH + off);
                    LDSM4(apl[mt][0], apl[mt][1], apl[mt][2], apl[mt][3], sb + APL + off);
                }
                uint32_t vh[4][2], vl[4][2];
#pragma unroll
                for (int nh = 0; nh < 2; nh++) {
                    int r = ks * 16 + ((lane >> 4) << 3) + (lane & 7);
                    int gq = wn * 4 + nh * 2 + ((lane >> 3) & 1);
                    uint32_t off = (uint32_t)(r * 256 + ((gq ^ (r & 7)) << 4));
                    uint32_t r0, r1, r2, r3;
                    LDSM4T(r0, r1, r2, r3, sb + AVH + off);
                    vh[nh * 2][0] = r0; vh[nh * 2][1] = r2;
                    vh[nh * 2 + 1][0] = r1; vh[nh * 2 + 1][1] = r3;
                    LDSM4T(r0, r1, r2, r3, sb + AVL + off);
                    vl[nh * 2][0] = r0; vl[nh * 2][1] = r2;
                    vl[nh * 2 + 1][0] = r1; vl[nh * 2 + 1][1] = r3;
                }
#pragma unroll
                for (int mt = 0; mt < 2; mt++)
#pragma unroll
                    for (int nv = 0; nv < 4; nv++) {
                        MMA16816(oacc[mt][nv], aph[mt], vh[nv]);
                        MMA16816(oacc[mt][nv], aph[mt], vl[nv]);
                        MMA16816(oacc[mt][nv], apl[mt], vh[nv]);
                    }
            }
            __syncthreads();
        }

        // ---- epilogue ----
#pragma unroll
        for (int mt = 0; mt < 2; mt++) {
            const int r0 = wm * 32 + mt * 16 + g4;
            const float inv0 = 1.f / l_s[r0];
            const float inv1 = 1.f / l_s[r0 + 8];
#pragma unroll
            for (int nv = 0; nv < 4; nv++) {
                const int col = wn * 32 + nv * 8 + tig * 2;
                *(float2*)(out + qbase + (size_t)r0 * H_ + col) =
                    make_float2(oacc[mt][nv][0] * inv0, oacc[mt][nv][1] * inv0);
                *(float2*)(out + qbase + (size_t)(r0 + 8) * H_ + col) =
                    make_float2(oacc[mt][nv][2] * inv1, oacc[mt][nv][3] * inv1);
            }
        }
    }
}

// ---------------------------------------------------------------------------
extern "C" void kernel_launch(void* const* d_in, const int* in_sizes, int n_in,
                              void* d_out, int out_size)
{
    const float* x  = (const float*)d_in[0];
    const float* Wq = (const float*)d_in[1];
    const float* Wk = (const float*)d_in[2];
    const float* Wv = (const float*)d_in[3];
    float* out = (float*)d_out;

    prep_w_kernel<<<384, 256>>>(Wq, Wk, Wv);

    cudaFuncSetAttribute(qkv_mma_kernel,
                         cudaFuncAttributeMaxDynamicSharedMemorySize, QK_SMEM);
    qkv_mma_kernel<<<dim3(128, 3), 256, QK_SMEM>>>(x);

    cudaFuncSetAttribute(attn_mma_kernel,
                         cudaFuncAttributeMaxDynamicSharedMemorySize, ATT_SMEM);
    attn_mma_kernel<<<dim3(16, 8), 256, ATT_SMEM>>>(out);
}

// round 6
// speedup vs baseline: 3.1976x; 1.1452x over previous
#include <cuda_runtime.h>
#include <cuda_bf16.h>
#include <math.h>
#include <stdint.h>

#define B_ 8
#define T_ 2048
#define D_ 1024
#define H_ 128
#define SCALE 0.08838834764831845f   // 1/sqrt(128)

__device__ __forceinline__ uint32_t smem_u32(const void* p) {
    uint32_t a;
    asm("{ .reg .u64 t; cvta.to.shared.u64 t, %1; cvt.u32.u64 %0, t; }"
        : "=r"(a) : "l"(p));
    return a;
}
__device__ __forceinline__ uint32_t pack_bf(float a, float b) {
    __nv_bfloat162 t = __floats2bfloat162_rn(a, b);
    return *reinterpret_cast<uint32_t*>(&t);
}

#define CP16(dst, src) \
    asm volatile("cp.async.cg.shared.global [%0], [%1], 16;" \
                 :: "r"(dst), "l"(src) : "memory")
#define CP_COMMIT() asm volatile("cp.async.commit_group;" ::: "memory")
#define CP_WAIT0()  asm volatile("cp.async.wait_group 0;" ::: "memory")
#define CP_WAIT1()  asm volatile("cp.async.wait_group 1;" ::: "memory")

#define LDSM4(r0, r1, r2, r3, addr) \
    asm volatile("ldmatrix.sync.aligned.m8n8.x4.shared.b16 {%0,%1,%2,%3}, [%4];" \
                 : "=r"(r0), "=r"(r1), "=r"(r2), "=r"(r3) : "r"(addr))
#define LDSM4T(r0, r1, r2, r3, addr) \
    asm volatile("ldmatrix.sync.aligned.m8n8.x4.trans.shared.b16 {%0,%1,%2,%3}, [%4];" \
                 : "=r"(r0), "=r"(r1), "=r"(r2), "=r"(r3) : "r"(addr))

#define MMA16816(d, a, b) \
    asm volatile("mma.sync.aligned.m16n8k16.row.col.f32.bf16.bf16.f32 " \
                 "{%0,%1,%2,%3},{%4,%5,%6,%7},{%8,%9},{%0,%1,%2,%3};" \
                 : "+f"((d)[0]), "+f"((d)[1]), "+f"((d)[2]), "+f"((d)[3]) \
                 : "r"((a)[0]), "r"((a)[1]), "r"((a)[2]), "r"((a)[3]), \
                   "r"((b)[0]), "r"((b)[1]))

// ---- device scratch ----
__device__ __nv_bfloat16 g_q_hi[(size_t)B_ * T_ * H_];
__device__ __nv_bfloat16 g_q_lo[(size_t)B_ * T_ * H_];
__device__ __nv_bfloat16 g_k_hi[(size_t)B_ * T_ * H_];
__device__ __nv_bfloat16 g_k_lo[(size_t)B_ * T_ * H_];
__device__ __nv_bfloat16 g_v_hi[(size_t)B_ * T_ * H_];
__device__ __nv_bfloat16 g_v_lo[(size_t)B_ * T_ * H_];
__device__ __nv_bfloat16 g_Wb_hi[384 * 1024];
__device__ __nv_bfloat16 g_Wb_lo[384 * 1024];
__device__ __nv_bfloat16 g_x_hi[(size_t)B_ * T_ * D_];
__device__ __nv_bfloat16 g_x_lo[(size_t)B_ * T_ * D_];

// ---------------------------------------------------------------------------
// Prep W: Wcat[n][k] = W{q,k,v}[k][n%128] as bf16 hi + lo.
// ---------------------------------------------------------------------------
__global__ __launch_bounds__(256) void prep_w_kernel(
    const float* __restrict__ Wq,
    const float* __restrict__ Wk,
    const float* __restrict__ Wv)
{
    const int n = blockIdx.x;
    const float* W = (n < 128) ? Wq : (n < 256 ? Wk : Wv);
    const int h = n & 127;
    for (int k = threadIdx.x; k < 1024; k += 256) {
        float w = W[(size_t)k * H_ + h];
        __nv_bfloat16 hi = __float2bfloat16(w);
        float lo = w - __bfloat162float(hi);
        g_Wb_hi[(size_t)n * 1024 + k] = hi;
        g_Wb_lo[(size_t)n * 1024 + k] = __float2bfloat16(lo);
    }
}

// ---------------------------------------------------------------------------
// Prep X: fp32 -> bf16 hi/lo, one shot. 4M float4 slots.
// ---------------------------------------------------------------------------
__global__ __launch_bounds__(256) void prep_x_kernel(const float* __restrict__ x)
{
    const size_t i = (size_t)blockIdx.x * 256 + threadIdx.x;
    float4 f = ((const float4*)x)[i];
    __nv_bfloat16 h0 = __float2bfloat16(f.x);
    __nv_bfloat16 h1 = __float2bfloat16(f.y);
    __nv_bfloat16 h2 = __float2bfloat16(f.z);
    __nv_bfloat16 h3 = __float2bfloat16(f.w);
    uint2 hv, lv;
    hv.x = (uint32_t)__bfloat16_as_ushort(h0) |
           ((uint32_t)__bfloat16_as_ushort(h1) << 16);
    hv.y = (uint32_t)__bfloat16_as_ushort(h2) |
           ((uint32_t)__bfloat16_as_ushort(h3) << 16);
    lv.x = pack_bf(f.x - __bfloat162float(h0), f.y - __bfloat162float(h1));
    lv.y = pack_bf(f.z - __bfloat162float(h2), f.w - __bfloat162float(h3));
    ((uint2*)g_x_hi)[i] = hv;
    ((uint2*)g_x_lo)[i] = lv;
}

// ---------------------------------------------------------------------------
// QKV GEMM via mma.sync bf16 split, cp.async double-buffered.
// Stage buffer (64KB): AH 0 | AL 16K | BH 32K | BL 48K.  Two stages = 128KB.
// ---------------------------------------------------------------------------
#define QSTAGE 65536
#define QK_SMEM 131072

__device__ __forceinline__ void qkv_issue(uint32_t dstbase, int m0, int n0,
                                          int k0, int tid)
{
#pragma unroll
    for (int i = 0; i < 4; i++) {
        int idx = i * 256 + tid;                 // 1024 granules per array
        int r = idx >> 3, g = idx & 7;
        uint32_t off = (uint32_t)(r * 128 + ((g ^ (r & 7)) << 4));
        const size_t ax = (size_t)(m0 + r) * D_ + k0 + g * 8;
        const size_t bx = (size_t)(n0 + r) * D_ + k0 + g * 8;
        CP16(dstbase + off,         g_x_hi + ax);
        CP16(dstbase + 16384 + off, g_x_lo + ax);
        CP16(dstbase + 32768 + off, g_Wb_hi + bx);
        CP16(dstbase + 49152 + off, g_Wb_lo + bx);
    }
}

__global__ __launch_bounds__(256, 1) void qkv_mma_kernel()
{
    extern __shared__ char smq[];
    const uint32_t sb = smem_u32(smq);
    const int tid  = threadIdx.x;
    const int lane = tid & 31, warp = tid >> 5;
    const int wm = warp >> 2, wn = warp & 3;
    const int m0 = blockIdx.x * 128;
    const int n0 = blockIdx.y * 128;

    float acc[4][4][4];
#pragma unroll
    for (int mt = 0; mt < 4; mt++)
#pragma unroll
        for (int nt = 0; nt < 4; nt++)
#pragma unroll
            for (int j = 0; j < 4; j++) acc[mt][nt][j] = 0.f;

    uint32_t a_rb[4], a_xr[4];
#pragma unroll
    for (int mt = 0; mt < 4; mt++) {
        int rowA = wm * 64 + mt * 16 + (lane & 15);
        a_rb[mt] = (uint32_t)(rowA * 128);
        a_xr[mt] = (uint32_t)((rowA & 7) << 4);
    }
    const uint32_t a_cb = (uint32_t)((lane >> 4) * 16);
    uint32_t b_rb[2], b_xr[2];
#pragma unroll
    for (int p = 0; p < 2; p++) {
        int nB = wn * 32 + p * 16 + ((lane >> 4) << 3) + (lane & 7);
        b_rb[p] = (uint32_t)(nB * 128);
        b_xr[p] = (uint32_t)((nB & 7) << 4);
    }
    const uint32_t b_cb = (uint32_t)(((lane >> 3) & 1) * 16);

    qkv_issue(sb, m0, n0, 0, tid);
    CP_COMMIT();

    for (int kc = 0; kc < 16; kc++) {
        if (kc < 15) {
            qkv_issue(sb + (uint32_t)(((kc + 1) & 1) * QSTAGE),
                      m0, n0, (kc + 1) * 64, tid);
            CP_COMMIT();
            CP_WAIT1();
        } else {
            CP_WAIT0();
        }
        __syncthreads();

        const uint32_t bufb = sb + (uint32_t)((kc & 1) * QSTAGE);
#pragma unroll
        for (int ks = 0; ks < 4; ks++) {
            const uint32_t acol = (a_cb + ks * 32);
            const uint32_t bcol = (b_cb + ks * 32);
            uint32_t ah[4][4], al[4][4];
#pragma unroll
            for (int mt = 0; mt < 4; mt++) {
                LDSM4(ah[mt][0], ah[mt][1], ah[mt][2], ah[mt][3],
                      bufb + a_rb[mt] + (acol ^ a_xr[mt]));
                LDSM4(al[mt][0], al[mt][1], al[mt][2], al[mt][3],
                      bufb + 16384 + a_rb[mt] + (acol ^ a_xr[mt]));
            }
            uint32_t bh[4][2], bl[4][2];
#pragma unroll
            for (int p = 0; p < 2; p++) {
                uint32_t r0, r1, r2, r3;
                LDSM4(r0, r1, r2, r3, bufb + 32768 + b_rb[p] + (bcol ^ b_xr[p]));
                bh[2 * p][0] = r0; bh[2 * p][1] = r1;
                bh[2 * p + 1][0] = r2; bh[2 * p + 1][1] = r3;
                LDSM4(r0, r1, r2, r3, bufb + 49152 + b_rb[p] + (bcol ^ b_xr[p]));
                bl[2 * p][0] = r0; bl[2 * p][1] = r1;
                bl[2 * p + 1][0] = r2; bl[2 * p + 1][1] = r3;
            }
#pragma unroll
            for (int mt = 0; mt < 4; mt++)
#pragma unroll
                for (int nt = 0; nt < 4; nt++) {
                    MMA16816(acc[mt][nt], ah[mt], bh[nt]);
                    MMA16816(acc[mt][nt], ah[mt], bl[nt]);
                    MMA16816(acc[mt][nt], al[mt], bh[nt]);
                }
        }
        __syncthreads();
    }

    // ---- epilogue: fp32 acc -> bf16 hi/lo arrays ----
    __nv_bfloat16* oh = (blockIdx.y == 0) ? g_q_hi : (blockIdx.y == 1 ? g_k_hi : g_v_hi);
    __nv_bfloat16* ol = (blockIdx.y == 0) ? g_q_lo : (blockIdx.y == 1 ? g_k_lo : g_v_lo);
    const int g = lane >> 2, tig = lane & 3;
#pragma unroll
    for (int mt = 0; mt < 4; mt++) {
        const int row0 = m0 + wm * 64 + mt * 16 + g;
#pragma unroll
        for (int nt = 0; nt < 4; nt++) {
            const int col = wn * 32 + nt * 8 + tig * 2;
#pragma unroll
            for (int h = 0; h < 2; h++) {
                const int row = row0 + h * 8;
                float a0 = acc[mt][nt][2 * h], a1 = acc[mt][nt][2 * h + 1];
                __nv_bfloat16 h0 = __float2bfloat16(a0);
                __nv_bfloat16 h1 = __float2bfloat16(a1);
                *(uint32_t*)(oh + (size_t)row * H_ + col) =
                    (uint32_t)__bfloat16_as_ushort(h0) |
                    ((uint32_t)__bfloat16_as_ushort(h1) << 16);
                *(uint32_t*)(ol + (size_t)row * H_ + col) =
                    pack_bf(a0 - __bfloat162float(h0), a1 - __bfloat162float(h1));
            }
        }
    }
}

// ---------------------------------------------------------------------------
// Flash attention via mma.sync bf16 split, cp.async double-buffered K/V.
// smem: QH 0 | QL 16K | KV stage0 32K..96K | KV stage1 96K..160K |
//       Ss 160K | Ph | Pl | stats.   KV stage: KH 0|KL 16K|VH 32K|VL 48K.
// ---------------------------------------------------------------------------
#define AQH 0
#define AQL 16384
#define AKV0 32768
#define KVBUF 65536
#define ASS 163840
#define APH 181248
#define APL 189440
#define AMS 197632
#define ALS 197888
#define ACS 198144
#define ATT_SMEM 198400

__device__ __forceinline__ void kv_issue(uint32_t dstbase, size_t kbase, int tid)
{
#pragma unroll
    for (int i = 0; i < 4; i++) {
        int idx = i * 256 + tid;                 // 1024 granules per array
        int r = idx >> 4, gq = idx & 15;
        uint32_t off = (uint32_t)(r * 256 + ((gq ^ (r & 7)) << 4));
        const size_t ge = kbase + (size_t)r * 128 + gq * 8;
        CP16(dstbase + off,         g_k_hi + ge);
        CP16(dstbase + 16384 + off, g_k_lo + ge);
        CP16(dstbase + 32768 + off, g_v_hi + ge);
        CP16(dstbase + 49152 + off, g_v_lo + ge);
    }
}

__global__ __launch_bounds__(256, 1) void attn_mma_kernel(float* __restrict__ out)
{
    extern __shared__ char smA[];
    const uint32_t sb = smem_u32(smA);
    float* Ss  = (float*)(smA + ASS);
    float* m_s = (float*)(smA + AMS);
    float* l_s = (float*)(smA + ALS);
    float* c_s = (float*)(smA + ACS);

    const int tid  = threadIdx.x;
    const int lane = tid & 31, warp = tid >> 5;
    const int wm = warp >> 2, wn = warp & 3;
    const int b  = blockIdx.y;
    const int ty = tid >> 4, tx = tid & 15;
    const int g4 = lane >> 2, tig = lane & 3;

    for (int pass = 0; pass < 2; pass++) {
        const int qt = pass ? (31 - (int)blockIdx.x) : (int)blockIdx.x;
        const size_t qbase = ((size_t)b * T_ + (size_t)qt * 64) * H_;
        const size_t batchbase = (size_t)b * T_ * H_;

        __syncthreads();
        // prefetch tile 0 into stage 0
        kv_issue(sb + AKV0, batchbase, tid);
        CP_COMMIT();

        if (tid < 64) { m_s[tid] = -INFINITY; l_s[tid] = 0.f; }
#pragma unroll
        for (int i = 0; i < 4; i++) {
            int idx = i * 256 + tid;
            int r = idx >> 4, gq = idx & 15;
            uint32_t off = (uint32_t)(r * 256 + ((gq ^ (r & 7)) << 4));
            *(uint4*)(smA + AQH + off) = *(const uint4*)(g_q_hi + qbase + r * 128 + gq * 8);
            *(uint4*)(smA + AQL + off) = *(const uint4*)(g_q_lo + qbase + r * 128 + gq * 8);
        }
        float oacc[2][4][4];
#pragma unroll
        for (int mt = 0; mt < 2; mt++)
#pragma unroll
            for (int nv = 0; nv < 4; nv++)
#pragma unroll
                for (int j = 0; j < 4; j++) oacc[mt][nv][j] = 0.f;

        for (int kt = 0; kt <= qt; kt++) {
            if (kt < qt) {
                kv_issue(sb + AKV0 + (uint32_t)(((kt + 1) & 1) * KVBUF),
                         batchbase + (size_t)(kt + 1) * 64 * H_, tid);
                CP_COMMIT();
                CP_WAIT1();
            } else {
                CP_WAIT0();
            }
            __syncthreads();

            const uint32_t kvb = sb + AKV0 + (uint32_t)((kt & 1) * KVBUF);

            // ---- S = Q K^T (3-term bf16 split) ----
            float sacc[2][2][4];
#pragma unroll
            for (int mt = 0; mt < 2; mt++)
#pragma unroll
                for (int nt = 0; nt < 2; nt++)
#pragma unroll
                    for (int j = 0; j < 4; j++) sacc[mt][nt][j] = 0.f;

#pragma unroll
            for (int ks = 0; ks < 8; ks++) {
                uint32_t ah[2][4], al[2][4];
#pragma unroll
                for (int mt = 0; mt < 2; mt++) {
                    int r = wm * 32 + mt * 16 + (lane & 15);
                    int gq = ks * 2 + (lane >> 4);
                    uint32_t off = (uint32_t)(r * 256 + ((gq ^ (r & 7)) << 4));
                    LDSM4(ah[mt][0], ah[mt][1], ah[mt][2], ah[mt][3], sb + AQH + off);
                    LDSM4(al[mt][0], al[mt][1], al[mt][2], al[mt][3], sb + AQL + off);
                }
                uint32_t bh[2][2], bl[2][2];
                {
                    int r = wn * 16 + ((lane >> 4) << 3) + (lane & 7);
                    int gq = ks * 2 + ((lane >> 3) & 1);
                    uint32_t off = (uint32_t)(r * 256 + ((gq ^ (r & 7)) << 4));
                    uint32_t r0, r1, r2, r3;
                    LDSM4(r0, r1, r2, r3, kvb + off);
                    bh[0][0] = r0; bh[0][1] = r1; bh[1][0] = r2; bh[1][1] = r3;
                    LDSM4(r0, r1, r2, r3, kvb + 16384 + off);
                    bl[0][0] = r0; bl[0][1] = r1; bl[1][0] = r2; bl[1][1] = r3;
                }
#pragma unroll
                for (int mt = 0; mt < 2; mt++)
#pragma unroll
                    for (int nt = 0; nt < 2; nt++) {
                        MMA16816(sacc[mt][nt], ah[mt], bh[nt]);
                        MMA16816(sacc[mt][nt], ah[mt], bl[nt]);
                        MMA16816(sacc[mt][nt], al[mt], bh[nt]);
                    }
            }
#pragma unroll
            for (int mt = 0; mt < 2; mt++)
#pragma unroll
                for (int nt = 0; nt < 2; nt++) {
                    int r = wm * 32 + mt * 16 + g4;
                    int c = wn * 16 + nt * 8 + tig * 2;
                    *(float2*)&Ss[r * 68 + c] =
                        make_float2(sacc[mt][nt][0], sacc[mt][nt][1]);
                    *(float2*)&Ss[(r + 8) * 68 + c] =
                        make_float2(sacc[mt][nt][2], sacc[mt][nt][3]);
                }
            __syncthreads();

            // ---- softmax (half-warp per row-group) ----
#pragma unroll
            for (int i = 0; i < 4; i++) {
                const int r = ty * 4 + i;
                float4 sv = *(float4*)&Ss[r * 68 + tx * 4];
                float sc[4] = {sv.x * SCALE, sv.y * SCALE, sv.z * SCALE, sv.w * SCALE};
                float rm = -INFINITY;
#pragma unroll
                for (int j = 0; j < 4; j++) {
                    if (kt == qt && (tx * 4 + j) > r) sc[j] = -INFINITY;
                    rm = fmaxf(rm, sc[j]);
                }
#pragma unroll
                for (int d = 1; d < 16; d <<= 1)
                    rm = fmaxf(rm, __shfl_xor_sync(0xffffffffu, rm, d));
                const float mold = m_s[r];
                const float mnew = fmaxf(mold, rm);
                float p[4], rs = 0.f;
#pragma unroll
                for (int j = 0; j < 4; j++) { p[j] = __expf(sc[j] - mnew); rs += p[j]; }
                __nv_bfloat16 ph0 = __float2bfloat16(p[0]);
                __nv_bfloat16 ph1 = __float2bfloat16(p[1]);
                __nv_bfloat16 ph2 = __float2bfloat16(p[2]);
                __nv_bfloat16 ph3 = __float2bfloat16(p[3]);
                uint2 hv, lv;
                hv.x = (uint32_t)__bfloat16_as_ushort(ph0) |
                       ((uint32_t)__bfloat16_as_ushort(ph1) << 16);
                hv.y = (uint32_t)__bfloat16_as_ushort(ph2) |
                       ((uint32_t)__bfloat16_as_ushort(ph3) << 16);
                lv.x = pack_bf(p[0] - __bfloat162float(ph0), p[1] - __bfloat162float(ph1));
                lv.y = pack_bf(p[2] - __bfloat162float(ph2), p[3] - __bfloat162float(ph3));
                uint32_t off = (uint32_t)(r * 128 + (((tx >> 1) ^ (r & 7)) << 4) + (tx & 1) * 8);
                *(uint2*)(smA + APH + off) = hv;
                *(uint2*)(smA + APL + off) = lv;
#pragma unroll
                for (int d = 1; d < 16; d <<= 1)
                    rs += __shfl_xor_sync(0xffffffffu, rs, d);
                if (tx == 0) {
                    float corr = __expf(mold - mnew);
                    c_s[r] = corr;
                    l_s[r] = l_s[r] * corr + rs;
                    m_s[r] = mnew;
                }
            }
            __syncthreads();

            // ---- O *= corr ; O += P V (3-term) ----
#pragma unroll
            for (int mt = 0; mt < 2; mt++) {
                const int r0 = wm * 32 + mt * 16 + g4;
                float c0 = c_s[r0], c1 = c_s[r0 + 8];
#pragma unroll
                for (int nv = 0; nv < 4; nv++) {
                    oacc[mt][nv][0] *= c0; oacc[mt][nv][1] *= c0;
                    oacc[mt][nv][2] *= c1; oacc[mt][nv][3] *= c1;
                }
            }
#pragma unroll
            for (int ks = 0; ks < 4; ks++) {
                uint32_t aph[2][4], apl[2][4];
#pragma unroll
                for (int mt = 0; mt < 2; mt++) {
                    int r = wm * 32 + mt * 16 + (lane & 15);
                    int gq = ks * 2 + (lane >> 4);
                    uint32_t off = (uint32_t)(r * 128 + ((gq ^ (r & 7)) << 4));
                    LDSM4(aph[mt][0], aph[mt][1], aph[mt][2], aph[mt][3], sb + APH + off);
                    LDSM4(apl[mt][0], apl[mt][1], apl[mt][2], apl[mt][3], sb + APL + off);
                }
                uint32_t vh[4][2], vl[4][2];
#pragma unroll
                for (int nh = 0; nh < 2; nh++) {
                    int r = ks * 16 + ((lane >> 4) << 3) + (lane & 7);
                    int gq = wn * 4 + nh * 2 + ((lane >> 3) & 1);
                    uint32_t off = (uint32_t)(r * 256 + ((gq ^ (r & 7)) << 4));
                    uint32_t r0, r1, r2, r3;
                    LDSM4T(r0, r1, r2, r3, kvb + 32768 + off);
                    vh[nh * 2][0] = r0; vh[nh * 2][1] = r2;
                    vh[nh * 2 + 1][0] = r1; vh[nh * 2 + 1][1] = r3;
                    LDSM4T(r0, r1, r2, r3, kvb + 49152 + off);
                    vl[nh * 2][0] = r0; vl[nh * 2][1] = r2;
                    vl[nh * 2 + 1][0] = r1; vl[nh * 2 + 1][1] = r3;
                }
#pragma unroll
                for (int mt = 0; mt < 2; mt++)
#pragma unroll
                    for (int nv = 0; nv < 4; nv++) {
                        MMA16816(oacc[mt][nv], aph[mt], vh[nv]);
                        MMA16816(oacc[mt][nv], aph[mt], vl[nv]);
                        MMA16816(oacc[mt][nv], apl[mt], vh[nv]);
                    }
            }
            __syncthreads();
        }

        // ---- epilogue ----
#pragma unroll
        for (int mt = 0; mt < 2; mt++) {
            const int r0 = wm * 32 + mt * 16 + g4;
            const float inv0 = 1.f / l_s[r0];
            const float inv1 = 1.f / l_s[r0 + 8];
#pragma unroll
            for (int nv = 0; nv < 4; nv++) {
                const int col = wn * 32 + nv * 8 + tig * 2;
                *(float2*)(out + qbase + (size_t)r0 * H_ + col) =
                    make_float2(oacc[mt][nv][0] * inv0, oacc[mt][nv][1] * inv0);
                *(float2*)(out + qbase + (size_t)(r0 + 8) * H_ + col) =
                    make_float2(oacc[mt][nv][2] * inv1, oacc[mt][nv][3] * inv1);
            }
        }
    }
}

// ---------------------------------------------------------------------------
extern "C" void kernel_launch(void* const* d_in, const int* in_sizes, int n_in,
                              void* d_out, int out_size)
{
    const float* x  = (const float*)d_in[0];
    const float* Wq = (const float*)d_in[1];
    const float* Wk = (const float*)d_in[2];
    const float* Wv = (const float*)d_in[3];
    float* out = (float*)d_out;

    prep_w_kernel<<<384, 256>>>(Wq, Wk, Wv);
    prep_x_kernel<<<16384, 256>>>(x);

    cudaFuncSetAttribute(qkv_mma_kernel,
                         cudaFuncAttributeMaxDynamicSharedMemorySize, QK_SMEM);
    qkv_mma_kernel<<<dim3(128, 3), 256, QK_SMEM>>>();

    cudaFuncSetAttribute(attn_mma_kernel,
                         cudaFuncAttributeMaxDynamicSharedMemorySize, ATT_SMEM);
    attn_mma_kernel<<<dim3(16, 8), 256, ATT_SMEM>>>(out);
}

// round 7
// speedup vs baseline: 3.3518x; 1.0482x over previous
#include <cuda_runtime.h>
#include <cuda_bf16.h>
#include <math.h>
#include <stdint.h>

#define B_ 8
#define T_ 2048
#define D_ 1024
#define H_ 128
#define SCALE 0.08838834764831845f   // 1/sqrt(128)

__device__ __forceinline__ uint32_t smem_u32(const void* p) {
    uint32_t a;
    asm("{ .reg .u64 t; cvta.to.shared.u64 t, %1; cvt.u32.u64 %0, t; }"
        : "=r"(a) : "l"(p));
    return a;
}
__device__ __forceinline__ uint32_t pack_bf(float a, float b) {
    __nv_bfloat162 t = __floats2bfloat162_rn(a, b);
    return *reinterpret_cast<uint32_t*>(&t);
}

#define CP16(dst, src) \
    asm volatile("cp.async.cg.shared.global [%0], [%1], 16;" \
                 :: "r"(dst), "l"(src) : "memory")
#define CP_COMMIT() asm volatile("cp.async.commit_group;" ::: "memory")
#define CP_WAIT0()  asm volatile("cp.async.wait_group 0;" ::: "memory")
#define CP_WAIT1()  asm volatile("cp.async.wait_group 1;" ::: "memory")

#define LDSM4(r0, r1, r2, r3, addr) \
    asm volatile("ldmatrix.sync.aligned.m8n8.x4.shared.b16 {%0,%1,%2,%3}, [%4];" \
                 : "=r"(r0), "=r"(r1), "=r"(r2), "=r"(r3) : "r"(addr))
#define LDSM4T(r0, r1, r2, r3, addr) \
    asm volatile("ldmatrix.sync.aligned.m8n8.x4.trans.shared.b16 {%0,%1,%2,%3}, [%4];" \
                 : "=r"(r0), "=r"(r1), "=r"(r2), "=r"(r3) : "r"(addr))

#define MMA16816(d, a, b) \
    asm volatile("mma.sync.aligned.m16n8k16.row.col.f32.bf16.bf16.f32 " \
                 "{%0,%1,%2,%3},{%4,%5,%6,%7},{%8,%9},{%0,%1,%2,%3};" \
                 : "+f"((d)[0]), "+f"((d)[1]), "+f"((d)[2]), "+f"((d)[3]) \
                 : "r"((a)[0]), "r"((a)[1]), "r"((a)[2]), "r"((a)[3]), \
                   "r"((b)[0]), "r"((b)[1]))

// ---- device scratch ----
__device__ __nv_bfloat16 g_q_hi[(size_t)B_ * T_ * H_];
__device__ __nv_bfloat16 g_q_lo[(size_t)B_ * T_ * H_];
__device__ __nv_bfloat16 g_k_hi[(size_t)B_ * T_ * H_];
__device__ __nv_bfloat16 g_k_lo[(size_t)B_ * T_ * H_];
__device__ __nv_bfloat16 g_v_hi[(size_t)B_ * T_ * H_];
__device__ __nv_bfloat16 g_v_lo[(size_t)B_ * T_ * H_];
__device__ __nv_bfloat16 g_Wb_hi[384 * 1024];
__device__ __nv_bfloat16 g_Wb_lo[384 * 1024];
__device__ __nv_bfloat16 g_x_hi[(size_t)B_ * T_ * D_];
__device__ __nv_bfloat16 g_x_lo[(size_t)B_ * T_ * D_];

// ---------------------------------------------------------------------------
// Prep W
// ---------------------------------------------------------------------------
__global__ __launch_bounds__(256) void prep_w_kernel(
    const float* __restrict__ Wq,
    const float* __restrict__ Wk,
    const float* __restrict__ Wv)
{
    const int n = blockIdx.x;
    const float* W = (n < 128) ? Wq : (n < 256 ? Wk : Wv);
    const int h = n & 127;
    for (int k = threadIdx.x; k < 1024; k += 256) {
        float w = W[(size_t)k * H_ + h];
        __nv_bfloat16 hi = __float2bfloat16(w);
        float lo = w - __bfloat162float(hi);
        g_Wb_hi[(size_t)n * 1024 + k] = hi;
        g_Wb_lo[(size_t)n * 1024 + k] = __float2bfloat16(lo);
    }
}

// ---------------------------------------------------------------------------
// Prep X
// ---------------------------------------------------------------------------
__global__ __launch_bounds__(256) void prep_x_kernel(const float* __restrict__ x)
{
    const size_t i = (size_t)blockIdx.x * 256 + threadIdx.x;
    float4 f = ((const float4*)x)[i];
    __nv_bfloat16 h0 = __float2bfloat16(f.x);
    __nv_bfloat16 h1 = __float2bfloat16(f.y);
    __nv_bfloat16 h2 = __float2bfloat16(f.z);
    __nv_bfloat16 h3 = __float2bfloat16(f.w);
    uint2 hv, lv;
    hv.x = (uint32_t)__bfloat16_as_ushort(h0) |
           ((uint32_t)__bfloat16_as_ushort(h1) << 16);
    hv.y = (uint32_t)__bfloat16_as_ushort(h2) |
           ((uint32_t)__bfloat16_as_ushort(h3) << 16);
    lv.x = pack_bf(f.x - __bfloat162float(h0), f.y - __bfloat162float(h1));
    lv.y = pack_bf(f.z - __bfloat162float(h2), f.w - __bfloat162float(h3));
    ((uint2*)g_x_hi)[i] = hv;
    ((uint2*)g_x_lo)[i] = lv;
}

// ---------------------------------------------------------------------------
// QKV GEMM (unchanged from R6)
// ---------------------------------------------------------------------------
#define QSTAGE 65536
#define QK_SMEM 131072

__device__ __forceinline__ void qkv_issue(uint32_t dstbase, int m0, int n0,
                                          int k0, int tid)
{
#pragma unroll
    for (int i = 0; i < 4; i++) {
        int idx = i * 256 + tid;
        int r = idx >> 3, g = idx & 7;
        uint32_t off = (uint32_t)(r * 128 + ((g ^ (r & 7)) << 4));
        const size_t ax = (size_t)(m0 + r) * D_ + k0 + g * 8;
        const size_t bx = (size_t)(n0 + r) * D_ + k0 + g * 8;
        CP16(dstbase + off,         g_x_hi + ax);
        CP16(dstbase + 16384 + off, g_x_lo + ax);
        CP16(dstbase + 32768 + off, g_Wb_hi + bx);
        CP16(dstbase + 49152 + off, g_Wb_lo + bx);
    }
}

__global__ __launch_bounds__(256, 1) void qkv_mma_kernel()
{
    extern __shared__ char smq[];
    const uint32_t sb = smem_u32(smq);
    const int tid  = threadIdx.x;
    const int lane = tid & 31, warp = tid >> 5;
    const int wm = warp >> 2, wn = warp & 3;
    const int m0 = blockIdx.x * 128;
    const int n0 = blockIdx.y * 128;

    float acc[4][4][4];
#pragma unroll
    for (int mt = 0; mt < 4; mt++)
#pragma unroll
        for (int nt = 0; nt < 4; nt++)
#pragma unroll
            for (int j = 0; j < 4; j++) acc[mt][nt][j] = 0.f;

    uint32_t a_rb[4], a_xr[4];
#pragma unroll
    for (int mt = 0; mt < 4; mt++) {
        int rowA = wm * 64 + mt * 16 + (lane & 15);
        a_rb[mt] = (uint32_t)(rowA * 128);
        a_xr[mt] = (uint32_t)((rowA & 7) << 4);
    }
    const uint32_t a_cb = (uint32_t)((lane >> 4) * 16);
    uint32_t b_rb[2], b_xr[2];
#pragma unroll
    for (int p = 0; p < 2; p++) {
        int nB = wn * 32 + p * 16 + ((lane >> 4) << 3) + (lane & 7);
        b_rb[p] = (uint32_t)(nB * 128);
        b_xr[p] = (uint32_t)((nB & 7) << 4);
    }
    const uint32_t b_cb = (uint32_t)(((lane >> 3) & 1) * 16);

    qkv_issue(sb, m0, n0, 0, tid);
    CP_COMMIT();

    for (int kc = 0; kc < 16; kc++) {
        if (kc < 15) {
            qkv_issue(sb + (uint32_t)(((kc + 1) & 1) * QSTAGE),
                      m0, n0, (kc + 1) * 64, tid);
            CP_COMMIT();
            CP_WAIT1();
        } else {
            CP_WAIT0();
        }
        __syncthreads();

        const uint32_t bufb = sb + (uint32_t)((kc & 1) * QSTAGE);
#pragma unroll
        for (int ks = 0; ks < 4; ks++) {
            const uint32_t acol = (a_cb + ks * 32);
            const uint32_t bcol = (b_cb + ks * 32);
            uint32_t ah[4][4], al[4][4];
#pragma unroll
            for (int mt = 0; mt < 4; mt++) {
                LDSM4(ah[mt][0], ah[mt][1], ah[mt][2], ah[mt][3],
                      bufb + a_rb[mt] + (acol ^ a_xr[mt]));
                LDSM4(al[mt][0], al[mt][1], al[mt][2], al[mt][3],
                      bufb + 16384 + a_rb[mt] + (acol ^ a_xr[mt]));
            }
            uint32_t bh[4][2], bl[4][2];
#pragma unroll
            for (int p = 0; p < 2; p++) {
                uint32_t r0, r1, r2, r3;
                LDSM4(r0, r1, r2, r3, bufb + 32768 + b_rb[p] + (bcol ^ b_xr[p]));
                bh[2 * p][0] = r0; bh[2 * p][1] = r1;
                bh[2 * p + 1][0] = r2; bh[2 * p + 1][1] = r3;
                LDSM4(r0, r1, r2, r3, bufb + 49152 + b_rb[p] + (bcol ^ b_xr[p]));
                bl[2 * p][0] = r0; bl[2 * p][1] = r1;
                bl[2 * p + 1][0] = r2; bl[2 * p + 1][1] = r3;
            }
#pragma unroll
            for (int mt = 0; mt < 4; mt++)
#pragma unroll
                for (int nt = 0; nt < 4; nt++) {
                    MMA16816(acc[mt][nt], ah[mt], bh[nt]);
                    MMA16816(acc[mt][nt], ah[mt], bl[nt]);
                    MMA16816(acc[mt][nt], al[mt], bh[nt]);
                }
        }
        __syncthreads();
    }

    __nv_bfloat16* oh = (blockIdx.y == 0) ? g_q_hi : (blockIdx.y == 1 ? g_k_hi : g_v_hi);
    __nv_bfloat16* ol = (blockIdx.y == 0) ? g_q_lo : (blockIdx.y == 1 ? g_k_lo : g_v_lo);
    const int g = lane >> 2, tig = lane & 3;
#pragma unroll
    for (int mt = 0; mt < 4; mt++) {
        const int row0 = m0 + wm * 64 + mt * 16 + g;
#pragma unroll
        for (int nt = 0; nt < 4; nt++) {
            const int col = wn * 32 + nt * 8 + tig * 2;
#pragma unroll
            for (int h = 0; h < 2; h++) {
                const int row = row0 + h * 8;
                float a0 = acc[mt][nt][2 * h], a1 = acc[mt][nt][2 * h + 1];
                __nv_bfloat16 h0 = __float2bfloat16(a0);
                __nv_bfloat16 h1 = __float2bfloat16(a1);
                *(uint32_t*)(oh + (size_t)row * H_ + col) =
                    (uint32_t)__bfloat16_as_ushort(h0) |
                    ((uint32_t)__bfloat16_as_ushort(h1) << 16);
                *(uint32_t*)(ol + (size_t)row * H_ + col) =
                    pack_bf(a0 - __bfloat162float(h0), a1 - __bfloat162float(h1));
            }
        }
    }
}

// ---------------------------------------------------------------------------
// Flash attention: 128 threads, 4 warps, each warp owns 16 rows x full width.
// Register-resident softmax + in-register P fragments. KV double-buffered.
// smem: QH 0 | QL 16K | KV stage0 32K (KH|KL|VH|VL 16K each) | stage1 96K.
// ---------------------------------------------------------------------------
#define AQH 0
#define AQL 16384
#define AKV0 32768
#define KVBUF 65536
#define ATT_SMEM 163840

__device__ __forceinline__ void kv_issue128(uint32_t dstbase, size_t kbase, int tid)
{
#pragma unroll
    for (int i = 0; i < 8; i++) {
        int idx = i * 128 + tid;                 // 1024 granules per array
        int r = idx >> 4, gq = idx & 15;
        uint32_t off = (uint32_t)(r * 256 + ((gq ^ (r & 7)) << 4));
        const size_t ge = kbase + (size_t)r * 128 + gq * 8;
        CP16(dstbase + off,         g_k_hi + ge);
        CP16(dstbase + 16384 + off, g_k_lo + ge);
        CP16(dstbase + 32768 + off, g_v_hi + ge);
        CP16(dstbase + 49152 + off, g_v_lo + ge);
    }
}

__global__ __launch_bounds__(128, 1) void attn_mma_kernel(float* __restrict__ out)
{
    extern __shared__ char smA[];
    const uint32_t sb = smem_u32(smA);

    const int tid  = threadIdx.x;
    const int lane = tid & 31, w = tid >> 5;
    const int b    = blockIdx.y;
    const int g4   = lane >> 2, tig = lane & 3;
    const int b3   = (lane >> 3) & 1;
    const int rk   = ((lane >> 4) << 3) + (lane & 7);   // ldsm B-row-within-16
    const int xr7  = lane & 7;

    for (int pass = 0; pass < 2; pass++) {
        const int qt = pass ? (31 - (int)blockIdx.x) : (int)blockIdx.x;
        const size_t qbase = ((size_t)b * T_ + (size_t)qt * 64) * H_;
        const size_t batchbase = (size_t)b * T_ * H_;

        __syncthreads();                 // previous pass fully done with smem
        kv_issue128(sb + AKV0, batchbase, tid);
        CP_COMMIT();

        // stage Q into smem, then pull Q fragments into registers
#pragma unroll
        for (int i = 0; i < 8; i++) {
            int idx = i * 128 + tid;
            int r = idx >> 4, gq = idx & 15;
            uint32_t off = (uint32_t)(r * 256 + ((gq ^ (r & 7)) << 4));
            *(uint4*)(smA + AQH + off) = *(const uint4*)(g_q_hi + qbase + r * 128 + gq * 8);
            *(uint4*)(smA + AQL + off) = *(const uint4*)(g_q_lo + qbase + r * 128 + gq * 8);
        }
        __syncthreads();

        uint32_t qh[8][4], ql[8][4];
        {
            const int r = w * 16 + (lane & 15);
#pragma unroll
            for (int ks = 0; ks < 8; ks++) {
                int gq = ks * 2 + (lane >> 4);
                uint32_t off = (uint32_t)(r * 256 + ((gq ^ (r & 7)) << 4));
                LDSM4(qh[ks][0], qh[ks][1], qh[ks][2], qh[ks][3], sb + AQH + off);
                LDSM4(ql[ks][0], ql[ks][1], ql[ks][2], ql[ks][3], sb + AQL + off);
            }
        }

        float oacc[16][4];
#pragma unroll
        for (int t = 0; t < 16; t++)
#pragma unroll
            for (int j = 0; j < 4; j++) oacc[t][j] = 0.f;
        float m0 = -INFINITY, m1 = -INFINITY, l0 = 0.f, l1 = 0.f;

        for (int kt = 0; kt <= qt; kt++) {
            if (kt < qt) {
                kv_issue128(sb + AKV0 + (uint32_t)(((kt + 1) & 1) * KVBUF),
                            batchbase + (size_t)(kt + 1) * 64 * H_, tid);
                CP_COMMIT();
                CP_WAIT1();
            } else {
                CP_WAIT0();
            }
            __syncthreads();
            const uint32_t kvb = sb + AKV0 + (uint32_t)((kt & 1) * KVBUF);

            // ---- S = Q K^T (3-term) ----
            float sacc[8][4];
#pragma unroll
            for (int nt = 0; nt < 8; nt++)
#pragma unroll
                for (int j = 0; j < 4; j++) sacc[nt][j] = 0.f;

#pragma unroll
            for (int ks = 0; ks < 8; ks++) {
                const int gq = ks * 2 + b3;
                const uint32_t csw = (uint32_t)((gq ^ xr7) << 4);
#pragma unroll
                for (int p = 0; p < 4; p++) {
                    const uint32_t off = (uint32_t)((p * 16 + rk) * 256) + csw;
                    uint32_t h0, h1, h2, h3, lo0, lo1, lo2, lo3;
                    LDSM4(h0, h1, h2, h3, kvb + off);
                    LDSM4(lo0, lo1, lo2, lo3, kvb + 16384 + off);
                    uint32_t bh0[2] = {h0, h1}, bh1[2] = {h2, h3};
                    uint32_t bl0[2] = {lo0, lo1}, bl1[2] = {lo2, lo3};
                    MMA16816(sacc[2 * p],     qh[ks], bh0);
                    MMA16816(sacc[2 * p],     qh[ks], bl0);
                    MMA16816(sacc[2 * p],     ql[ks], bh0);
                    MMA16816(sacc[2 * p + 1], qh[ks], bh1);
                    MMA16816(sacc[2 * p + 1], qh[ks], bl1);
                    MMA16816(sacc[2 * p + 1], ql[ks], bh1);
                }
            }

            // ---- register softmax ----
#pragma unroll
            for (int nt = 0; nt < 8; nt++)
#pragma unroll
                for (int j = 0; j < 4; j++) sacc[nt][j] *= SCALE;

            if (kt == qt) {
                const int r0g = w * 16 + g4, r1g = r0g + 8;
#pragma unroll
                for (int nt = 0; nt < 8; nt++) {
                    const int c0 = nt * 8 + tig * 2, c1 = c0 + 1;
                    if (c0 > r0g) sacc[nt][0] = -INFINITY;
                    if (c1 > r0g) sacc[nt][1] = -INFINITY;
                    if (c0 > r1g) sacc[nt][2] = -INFINITY;
                    if (c1 > r1g) sacc[nt][3] = -INFINITY;
                }
            }

            float rm0 = -INFINITY, rm1 = -INFINITY;
#pragma unroll
            for (int nt = 0; nt < 8; nt++) {
                rm0 = fmaxf(rm0, fmaxf(sacc[nt][0], sacc[nt][1]));
                rm1 = fmaxf(rm1, fmaxf(sacc[nt][2], sacc[nt][3]));
            }
            rm0 = fmaxf(rm0, __shfl_xor_sync(0xffffffffu, rm0, 1));
            rm0 = fmaxf(rm0, __shfl_xor_sync(0xffffffffu, rm0, 2));
            rm1 = fmaxf(rm1, __shfl_xor_sync(0xffffffffu, rm1, 1));
            rm1 = fmaxf(rm1, __shfl_xor_sync(0xffffffffu, rm1, 2));

            const float mn0 = fmaxf(m0, rm0), mn1 = fmaxf(m1, rm1);
            const float corr0 = __expf(m0 - mn0), corr1 = __expf(m1 - mn1);
            m0 = mn0; m1 = mn1;

            float rs0 = 0.f, rs1 = 0.f;
#pragma unroll
            for (int nt = 0; nt < 8; nt++) {
                float p0 = __expf(sacc[nt][0] - mn0);
                float p1 = __expf(sacc[nt][1] - mn0);
                float p2 = __expf(sacc[nt][2] - mn1);
                float p3 = __expf(sacc[nt][3] - mn1);
                sacc[nt][0] = p0; sacc[nt][1] = p1;
                sacc[nt][2] = p2; sacc[nt][3] = p3;
                rs0 += p0 + p1; rs1 += p2 + p3;
            }
            rs0 += __shfl_xor_sync(0xffffffffu, rs0, 1);
            rs0 += __shfl_xor_sync(0xffffffffu, rs0, 2);
            rs1 += __shfl_xor_sync(0xffffffffu, rs1, 1);
            rs1 += __shfl_xor_sync(0xffffffffu, rs1, 2);
            l0 = l0 * corr0 + rs0;
            l1 = l1 * corr1 + rs1;

#pragma unroll
            for (int t = 0; t < 16; t++) {
                oacc[t][0] *= corr0; oacc[t][1] *= corr0;
                oacc[t][2] *= corr1; oacc[t][3] *= corr1;
            }

            // ---- P fragments in-register (A-frag layout) ----
            uint32_t ph[4][4], pl[4][4];
#pragma unroll
            for (int c = 0; c < 4; c++) {
#pragma unroll
                for (int half = 0; half < 2; half++) {
                    const int nt = 2 * c + half;
                    float a0 = sacc[nt][0], a1 = sacc[nt][1];
                    float a2 = sacc[nt][2], a3 = sacc[nt][3];
                    __nv_bfloat16 h0 = __float2bfloat16(a0);
                    __nv_bfloat16 h1 = __float2bfloat16(a1);
                    __nv_bfloat16 h2 = __float2bfloat16(a2);
                    __nv_bfloat16 h3 = __float2bfloat16(a3);
                    ph[c][2 * half] =
                        (uint32_t)__bfloat16_as_ushort(h0) |
                        ((uint32_t)__bfloat16_as_ushort(h1) << 16);
                    ph[c][2 * half + 1] =
                        (uint32_t)__bfloat16_as_ushort(h2) |
                        ((uint32_t)__bfloat16_as_ushort(h3) << 16);
                    pl[c][2 * half] =
                        pack_bf(a0 - __bfloat162float(h0), a1 - __bfloat162float(h1));
                    pl[c][2 * half + 1] =
                        pack_bf(a2 - __bfloat162float(h2), a3 - __bfloat162float(h3));
                }
            }

            // ---- O += P V (3-term) ----
#pragma unroll
            for (int c = 0; c < 4; c++) {
                const uint32_t roff = (uint32_t)((c * 16 + rk) * 256);
#pragma unroll
                for (int jp = 0; jp < 8; jp++) {
                    const int gq = jp * 2 + b3;
                    const uint32_t off = roff + (uint32_t)((gq ^ xr7) << 4);
                    uint32_t t0, t1, t2, t3, u0, u1, u2, u3;
                    LDSM4T(t0, t1, t2, t3, kvb + 32768 + off);
                    LDSM4T(u0, u1, u2, u3, kvb + 49152 + off);
                    uint32_t vh0[2] = {t0, t2}, vh1[2] = {t1, t3};
                    uint32_t vl0[2] = {u0, u2}, vl1[2] = {u1, u3};
                    MMA16816(oacc[2 * jp],     ph[c], vh0);
                    MMA16816(oacc[2 * jp],     ph[c], vl0);
                    MMA16816(oacc[2 * jp],     pl[c], vh0);
                    MMA16816(oacc[2 * jp + 1], ph[c], vh1);
                    MMA16816(oacc[2 * jp + 1], ph[c], vl1);
                    MMA16816(oacc[2 * jp + 1], pl[c], vh1);
                }
            }
            __syncthreads();   // all warps done with this KV stage
        }

        // ---- epilogue ----
        const float inv0 = 1.f / l0, inv1 = 1.f / l1;
        const int r0 = w * 16 + g4, r1 = r0 + 8;
#pragma unroll
        for (int t = 0; t < 16; t++) {
            const int col = t * 8 + tig * 2;
            *(float2*)(out + qbase + (size_t)r0 * H_ + col) =
                make_float2(oacc[t][0] * inv0, oacc[t][1] * inv0);
            *(float2*)(out + qbase + (size_t)r1 * H_ + col) =
                make_float2(oacc[t][2] * inv1, oacc[t][3] * inv1);
        }
    }
}

// ---------------------------------------------------------------------------
extern "C" void kernel_launch(void* const* d_in, const int* in_sizes, int n_in,
                              void* d_out, int out_size)
{
    const float* x  = (const float*)d_in[0];
    const float* Wq = (const float*)d_in[1];
    const float* Wk = (const float*)d_in[2];
    const float* Wv = (const float*)d_in[3];
    float* out = (float*)d_out;

    prep_w_kernel<<<384, 256>>>(Wq, Wk, Wv);
    prep_x_kernel<<<16384, 256>>>(x);

    cudaFuncSetAttribute(qkv_mma_kernel,
                         cudaFuncAttributeMaxDynamicSharedMemorySize, QK_SMEM);
    qkv_mma_kernel<<<dim3(128, 3), 256, QK_SMEM>>>();

    cudaFuncSetAttribute(attn_mma_kernel,
                         cudaFuncAttributeMaxDynamicSharedMemorySize, ATT_SMEM);
    attn_mma_kernel<<<dim3(16, 8), 128, ATT_SMEM>>>(out);
}

// round 8
// speedup vs baseline: 3.5393x; 1.0560x over previous
#include <cuda_runtime.h>
#include <cuda_bf16.h>
#include <math.h>
#include <stdint.h>

#define B_ 8
#define T_ 2048
#define D_ 1024
#define H_ 128
#define SCALE 0.08838834764831845f   // 1/sqrt(128)

__device__ __forceinline__ uint32_t smem_u32(const void* p) {
    uint32_t a;
    asm("{ .reg .u64 t; cvta.to.shared.u64 t, %1; cvt.u32.u64 %0, t; }"
        : "=r"(a) : "l"(p));
    return a;
}
__device__ __forceinline__ uint32_t pack_bf(float a, float b) {
    __nv_bfloat162 t = __floats2bfloat162_rn(a, b);
    return *reinterpret_cast<uint32_t*>(&t);
}

#define CP16(dst, src) \
    asm volatile("cp.async.cg.shared.global [%0], [%1], 16;" \
                 :: "r"(dst), "l"(src) : "memory")
#define CP_COMMIT() asm volatile("cp.async.commit_group;" ::: "memory")
#define CP_WAIT0()  asm volatile("cp.async.wait_group 0;" ::: "memory")
#define CP_WAIT1()  asm volatile("cp.async.wait_group 1;" ::: "memory")

#define LDSM4(r0, r1, r2, r3, addr) \
    asm volatile("ldmatrix.sync.aligned.m8n8.x4.shared.b16 {%0,%1,%2,%3}, [%4];" \
                 : "=r"(r0), "=r"(r1), "=r"(r2), "=r"(r3) : "r"(addr))
#define LDSM4T(r0, r1, r2, r3, addr) \
    asm volatile("ldmatrix.sync.aligned.m8n8.x4.trans.shared.b16 {%0,%1,%2,%3}, [%4];" \
                 : "=r"(r0), "=r"(r1), "=r"(r2), "=r"(r3) : "r"(addr))

#define MMA16816(d, a, b) \
    asm volatile("mma.sync.aligned.m16n8k16.row.col.f32.bf16.bf16.f32 " \
                 "{%0,%1,%2,%3},{%4,%5,%6,%7},{%8,%9},{%0,%1,%2,%3};" \
                 : "+f"((d)[0]), "+f"((d)[1]), "+f"((d)[2]), "+f"((d)[3]) \
                 : "r"((a)[0]), "r"((a)[1]), "r"((a)[2]), "r"((a)[3]), \
                   "r"((b)[0]), "r"((b)[1]))

// ---- device scratch ----
__device__ __nv_bfloat16 g_q_hi[(size_t)B_ * T_ * H_];
__device__ __nv_bfloat16 g_q_lo[(size_t)B_ * T_ * H_];
__device__ __nv_bfloat16 g_k_hi[(size_t)B_ * T_ * H_];
__device__ __nv_bfloat16 g_k_lo[(size_t)B_ * T_ * H_];
__device__ __nv_bfloat16 g_v_hi[(size_t)B_ * T_ * H_];
__device__ __nv_bfloat16 g_v_lo[(size_t)B_ * T_ * H_];
__device__ __nv_bfloat16 g_Wb_hi[384 * 1024];
__device__ __nv_bfloat16 g_Wb_lo[384 * 1024];
__device__ __nv_bfloat16 g_x_hi[(size_t)B_ * T_ * D_];
__device__ __nv_bfloat16 g_x_lo[(size_t)B_ * T_ * D_];

// ---------------------------------------------------------------------------
// Prep W
// ---------------------------------------------------------------------------
__global__ __launch_bounds__(256) void prep_w_kernel(
    const float* __restrict__ Wq,
    const float* __restrict__ Wk,
    const float* __restrict__ Wv)
{
    const int n = blockIdx.x;
    const float* W = (n < 128) ? Wq : (n < 256 ? Wk : Wv);
    const int h = n & 127;
    for (int k = threadIdx.x; k < 1024; k += 256) {
        float w = W[(size_t)k * H_ + h];
        __nv_bfloat16 hi = __float2bfloat16(w);
        float lo = w - __bfloat162float(hi);
        g_Wb_hi[(size_t)n * 1024 + k] = hi;
        g_Wb_lo[(size_t)n * 1024 + k] = __float2bfloat16(lo);
    }
}

// ---------------------------------------------------------------------------
// Prep X
// ---------------------------------------------------------------------------
__global__ __launch_bounds__(256) void prep_x_kernel(const float* __restrict__ x)
{
    const size_t i = (size_t)blockIdx.x * 256 + threadIdx.x;
    float4 f = ((const float4*)x)[i];
    __nv_bfloat16 h0 = __float2bfloat16(f.x);
    __nv_bfloat16 h1 = __float2bfloat16(f.y);
    __nv_bfloat16 h2 = __float2bfloat16(f.z);
    __nv_bfloat16 h3 = __float2bfloat16(f.w);
    uint2 hv, lv;
    hv.x = (uint32_t)__bfloat16_as_ushort(h0) |
           ((uint32_t)__bfloat16_as_ushort(h1) << 16);
    hv.y = (uint32_t)__bfloat16_as_ushort(h2) |
           ((uint32_t)__bfloat16_as_ushort(h3) << 16);
    lv.x = pack_bf(f.x - __bfloat162float(h0), f.y - __bfloat162float(h1));
    lv.y = pack_bf(f.z - __bfloat162float(h2), f.w - __bfloat162float(h3));
    ((uint2*)g_x_hi)[i] = hv;
    ((uint2*)g_x_lo)[i] = lv;
}

// ---------------------------------------------------------------------------
// QKV GEMM (unchanged from R6)
// ---------------------------------------------------------------------------
#define QSTAGE 65536
#define QK_SMEM 131072

__device__ __forceinline__ void qkv_issue(uint32_t dstbase, int m0, int n0,
                                          int k0, int tid)
{
#pragma unroll
    for (int i = 0; i < 4; i++) {
        int idx = i * 256 + tid;
        int r = idx >> 3, g = idx & 7;
        uint32_t off = (uint32_t)(r * 128 + ((g ^ (r & 7)) << 4));
        const size_t ax = (size_t)(m0 + r) * D_ + k0 + g * 8;
        const size_t bx = (size_t)(n0 + r) * D_ + k0 + g * 8;
        CP16(dstbase + off,         g_x_hi + ax);
        CP16(dstbase + 16384 + off, g_x_lo + ax);
        CP16(dstbase + 32768 + off, g_Wb_hi + bx);
        CP16(dstbase + 49152 + off, g_Wb_lo + bx);
    }
}

__global__ __launch_bounds__(256, 1) void qkv_mma_kernel()
{
    extern __shared__ char smq[];
    const uint32_t sb = smem_u32(smq);
    const int tid  = threadIdx.x;
    const int lane = tid & 31, warp = tid >> 5;
    const int wm = warp >> 2, wn = warp & 3;
    const int m0 = blockIdx.x * 128;
    const int n0 = blockIdx.y * 128;

    float acc[4][4][4];
#pragma unroll
    for (int mt = 0; mt < 4; mt++)
#pragma unroll
        for (int nt = 0; nt < 4; nt++)
#pragma unroll
            for (int j = 0; j < 4; j++) acc[mt][nt][j] = 0.f;

    uint32_t a_rb[4], a_xr[4];
#pragma unroll
    for (int mt = 0; mt < 4; mt++) {
        int rowA = wm * 64 + mt * 16 + (lane & 15);
        a_rb[mt] = (uint32_t)(rowA * 128);
        a_xr[mt] = (uint32_t)((rowA & 7) << 4);
    }
    const uint32_t a_cb = (uint32_t)((lane >> 4) * 16);
    uint32_t b_rb[2], b_xr[2];
#pragma unroll
    for (int p = 0; p < 2; p++) {
        int nB = wn * 32 + p * 16 + ((lane >> 4) << 3) + (lane & 7);
        b_rb[p] = (uint32_t)(nB * 128);
        b_xr[p] = (uint32_t)((nB & 7) << 4);
    }
    const uint32_t b_cb = (uint32_t)(((lane >> 3) & 1) * 16);

    qkv_issue(sb, m0, n0, 0, tid);
    CP_COMMIT();

    for (int kc = 0; kc < 16; kc++) {
        if (kc < 15) {
            qkv_issue(sb + (uint32_t)(((kc + 1) & 1) * QSTAGE),
                      m0, n0, (kc + 1) * 64, tid);
            CP_COMMIT();
            CP_WAIT1();
        } else {
            CP_WAIT0();
        }
        __syncthreads();

        const uint32_t bufb = sb + (uint32_t)((kc & 1) * QSTAGE);
#pragma unroll
        for (int ks = 0; ks < 4; ks++) {
            const uint32_t acol = (a_cb + ks * 32);
            const uint32_t bcol = (b_cb + ks * 32);
            uint32_t ah[4][4], al[4][4];
#pragma unroll
            for (int mt = 0; mt < 4; mt++) {
                LDSM4(ah[mt][0], ah[mt][1], ah[mt][2], ah[mt][3],
                      bufb + a_rb[mt] + (acol ^ a_xr[mt]));
                LDSM4(al[mt][0], al[mt][1], al[mt][2], al[mt][3],
                      bufb + 16384 + a_rb[mt] + (acol ^ a_xr[mt]));
            }
            uint32_t bh[4][2], bl[4][2];
#pragma unroll
            for (int p = 0; p < 2; p++) {
                uint32_t r0, r1, r2, r3;
                LDSM4(r0, r1, r2, r3, bufb + 32768 + b_rb[p] + (bcol ^ b_xr[p]));
                bh[2 * p][0] = r0; bh[2 * p][1] = r1;
                bh[2 * p + 1][0] = r2; bh[2 * p + 1][1] = r3;
                LDSM4(r0, r1, r2, r3, bufb + 49152 + b_rb[p] + (bcol ^ b_xr[p]));
                bl[2 * p][0] = r0; bl[2 * p][1] = r1;
                bl[2 * p + 1][0] = r2; bl[2 * p + 1][1] = r3;
            }
#pragma unroll
            for (int mt = 0; mt < 4; mt++)
#pragma unroll
                for (int nt = 0; nt < 4; nt++) {
                    MMA16816(acc[mt][nt], ah[mt], bh[nt]);
                    MMA16816(acc[mt][nt], ah[mt], bl[nt]);
                    MMA16816(acc[mt][nt], al[mt], bh[nt]);
                }
        }
        __syncthreads();
    }

    __nv_bfloat16* oh = (blockIdx.y == 0) ? g_q_hi : (blockIdx.y == 1 ? g_k_hi : g_v_hi);
    __nv_bfloat16* ol = (blockIdx.y == 0) ? g_q_lo : (blockIdx.y == 1 ? g_k_lo : g_v_lo);
    const int g = lane >> 2, tig = lane & 3;
#pragma unroll
    for (int mt = 0; mt < 4; mt++) {
        const int row0 = m0 + wm * 64 + mt * 16 + g;
#pragma unroll
        for (int nt = 0; nt < 4; nt++) {
            const int col = wn * 32 + nt * 8 + tig * 2;
#pragma unroll
            for (int h = 0; h < 2; h++) {
                const int row = row0 + h * 8;
                float a0 = acc[mt][nt][2 * h], a1 = acc[mt][nt][2 * h + 1];
                __nv_bfloat16 h0 = __float2bfloat16(a0);
                __nv_bfloat16 h1 = __float2bfloat16(a1);
                *(uint32_t*)(oh + (size_t)row * H_ + col) =
                    (uint32_t)__bfloat16_as_ushort(h0) |
                    ((uint32_t)__bfloat16_as_ushort(h1) << 16);
                *(uint32_t*)(ol + (size_t)row * H_ + col) =
                    pack_bf(a0 - __bfloat162float(h0), a1 - __bfloat162float(h1));
            }
        }
    }
}

// ---------------------------------------------------------------------------
// Flash attention: 256 threads, 8 warps = 4 row-groups x 2 col-halves.
// Warp computes S[16 rows x 32 cols]; keeps K-split partial O[16 x 128];
// row stats merged via 512B smem exchange; O merged once per pass.
// smem: QH 0 | QL 16K | KV stage0 32K | stage1 96K | mPart/sPart @160K.
// ---------------------------------------------------------------------------
#define AQH 0
#define AQL 16384
#define AKV0 32768
#define KVBUF 65536
#define AEXM 163840
#define AEXS 164352
#define ATT_SMEM 164864

__device__ __forceinline__ void kv_issue256(uint32_t dstbase, size_t kbase, int tid)
{
#pragma unroll
    for (int i = 0; i < 4; i++) {
        int idx = i * 256 + tid;
        int r = idx >> 4, gq = idx & 15;
        uint32_t off = (uint32_t)(r * 256 + ((gq ^ (r & 7)) << 4));
        const size_t ge = kbase + (size_t)r * 128 + gq * 8;
        CP16(dstbase + off,         g_k_hi + ge);
        CP16(dstbase + 16384 + off, g_k_lo + ge);
        CP16(dstbase + 32768 + off, g_v_hi + ge);
        CP16(dstbase + 49152 + off, g_v_lo + ge);
    }
}

__global__ __launch_bounds__(256, 1) void attn_mma_kernel(float* __restrict__ out)
{
    extern __shared__ char smA[];
    const uint32_t sb = smem_u32(smA);
    float* mPart = (float*)(smA + AEXM);   // [2][64]
    float* sPart = (float*)(smA + AEXS);   // [2][64]

    const int tid  = threadIdx.x;
    const int lane = tid & 31, warp = tid >> 5;
    const int wr = warp & 3;        // row group (16 rows)
    const int wh = warp >> 2;       // col half (32 S-cols)
    const int b    = blockIdx.y;
    const int g4   = lane >> 2, tig = lane & 3;
    const int b3   = (lane >> 3) & 1;
    const int rk   = ((lane >> 4) << 3) + (lane & 7);
    const int xr7  = lane & 7;

    for (int pass = 0; pass < 2; pass++) {
        const int qt = pass ? (31 - (int)blockIdx.x) : (int)blockIdx.x;
        const size_t qbase = ((size_t)b * T_ + (size_t)qt * 64) * H_;
        const size_t batchbase = (size_t)b * T_ * H_;

        __syncthreads();
        kv_issue256(sb + AKV0, batchbase, tid);
        CP_COMMIT();

#pragma unroll
        for (int i = 0; i < 4; i++) {
            int idx = i * 256 + tid;
            int r = idx >> 4, gq = idx & 15;
            uint32_t off = (uint32_t)(r * 256 + ((gq ^ (r & 7)) << 4));
            *(uint4*)(smA + AQH + off) = *(const uint4*)(g_q_hi + qbase + r * 128 + gq * 8);
            *(uint4*)(smA + AQL + off) = *(const uint4*)(g_q_lo + qbase + r * 128 + gq * 8);
        }
        __syncthreads();

        uint32_t qh[8][4], ql[8][4];
        {
            const int r = wr * 16 + (lane & 15);
#pragma unroll
            for (int ks = 0; ks < 8; ks++) {
                int gq = ks * 2 + (lane >> 4);
                uint32_t off = (uint32_t)(r * 256 + ((gq ^ (r & 7)) << 4));
                LDSM4(qh[ks][0], qh[ks][1], qh[ks][2], qh[ks][3], sb + AQH + off);
                LDSM4(ql[ks][0], ql[ks][1], ql[ks][2], ql[ks][3], sb + AQL + off);
            }
        }

        float oacc[16][4];
#pragma unroll
        for (int t = 0; t < 16; t++)
#pragma unroll
            for (int j = 0; j < 4; j++) oacc[t][j] = 0.f;
        float m0 = -INFINITY, m1 = -INFINITY, l0 = 0.f, l1 = 0.f;

        const int r0 = wr * 16 + g4, r1 = r0 + 8;

        for (int kt = 0; kt <= qt; kt++) {
            if (kt < qt) {
                kv_issue256(sb + AKV0 + (uint32_t)(((kt + 1) & 1) * KVBUF),
                            batchbase + (size_t)(kt + 1) * 64 * H_, tid);
                CP_COMMIT();
                CP_WAIT1();
            } else {
                CP_WAIT0();
            }
            __syncthreads();
            const uint32_t kvb = sb + AKV0 + (uint32_t)((kt & 1) * KVBUF);

            // ---- S = Q K^T for this warp's 32 cols (3-term) ----
            float sacc[4][4];
#pragma unroll
            for (int nt = 0; nt < 4; nt++)
#pragma unroll
                for (int j = 0; j < 4; j++) sacc[nt][j] = 0.f;

#pragma unroll
            for (int ks = 0; ks < 8; ks++) {
                const int gq = ks * 2 + b3;
                const uint32_t csw = (uint32_t)((gq ^ xr7) << 4);
#pragma unroll
                for (int p = 0; p < 2; p++) {
                    const uint32_t off =
                        (uint32_t)((wh * 32 + p * 16 + rk) * 256) + csw;
                    uint32_t h0, h1, h2, h3, u0, u1, u2, u3;
                    LDSM4(h0, h1, h2, h3, kvb + off);
                    LDSM4(u0, u1, u2, u3, kvb + 16384 + off);
                    uint32_t bh0[2] = {h0, h1}, bh1[2] = {h2, h3};
                    uint32_t bl0[2] = {u0, u1}, bl1[2] = {u2, u3};
                    MMA16816(sacc[2 * p],     qh[ks], bh0);
                    MMA16816(sacc[2 * p],     qh[ks], bl0);
                    MMA16816(sacc[2 * p],     ql[ks], bh0);
                    MMA16816(sacc[2 * p + 1], qh[ks], bh1);
                    MMA16816(sacc[2 * p + 1], qh[ks], bl1);
                    MMA16816(sacc[2 * p + 1], ql[ks], bh1);
                }
            }

            // ---- scale + causal mask ----
#pragma unroll
            for (int nt = 0; nt < 4; nt++)
#pragma unroll
                for (int j = 0; j < 4; j++) sacc[nt][j] *= SCALE;
            if (kt == qt) {
#pragma unroll
                for (int nt = 0; nt < 4; nt++) {
                    const int c0 = wh * 32 + nt * 8 + tig * 2, c1 = c0 + 1;
                    if (c0 > r0) sacc[nt][0] = -INFINITY;
                    if (c1 > r0) sacc[nt][1] = -INFINITY;
                    if (c0 > r1) sacc[nt][2] = -INFINITY;
                    if (c1 > r1) sacc[nt][3] = -INFINITY;
                }
            }

            // ---- partial row max over 32 cols, exchange between halves ----
            float rm0 = -INFINITY, rm1 = -INFINITY;
#pragma unroll
            for (int nt = 0; nt < 4; nt++) {
                rm0 = fmaxf(rm0, fmaxf(sacc[nt][0], sacc[nt][1]));
                rm1 = fmaxf(rm1, fmaxf(sacc[nt][2], sacc[nt][3]));
            }
            rm0 = fmaxf(rm0, __shfl_xor_sync(0xffffffffu, rm0, 1));
            rm0 = fmaxf(rm0, __shfl_xor_sync(0xffffffffu, rm0, 2));
            rm1 = fmaxf(rm1, __shfl_xor_sync(0xffffffffu, rm1, 1));
            rm1 = fmaxf(rm1, __shfl_xor_sync(0xffffffffu, rm1, 2));
            if (tig == 0) {
                mPart[wh * 64 + r0] = rm0;
                mPart[wh * 64 + r1] = rm1;
            }
            __syncthreads();
            const float gm0 = fmaxf(mPart[r0], mPart[64 + r0]);
            const float gm1 = fmaxf(mPart[r1], mPart[64 + r1]);

            const float mn0 = fmaxf(m0, gm0), mn1 = fmaxf(m1, gm1);
            const float corr0 = __expf(m0 - mn0), corr1 = __expf(m1 - mn1);
            m0 = mn0; m1 = mn1;

            float rs0 = 0.f, rs1 = 0.f;
#pragma unroll
            for (int nt = 0; nt < 4; nt++) {
                float p0 = __expf(sacc[nt][0] - mn0);
                float p1 = __expf(sacc[nt][1] - mn0);
                float p2 = __expf(sacc[nt][2] - mn1);
                float p3 = __expf(sacc[nt][3] - mn1);
                sacc[nt][0] = p0; sacc[nt][1] = p1;
                sacc[nt][2] = p2; sacc[nt][3] = p3;
                rs0 += p0 + p1; rs1 += p2 + p3;
            }
            rs0 += __shfl_xor_sync(0xffffffffu, rs0, 1);
            rs0 += __shfl_xor_sync(0xffffffffu, rs0, 2);
            rs1 += __shfl_xor_sync(0xffffffffu, rs1, 1);
            rs1 += __shfl_xor_sync(0xffffffffu, rs1, 2);
            if (tig == 0) {
                sPart[wh * 64 + r0] = rs0;
                sPart[wh * 64 + r1] = rs1;
            }
            __syncthreads();
            l0 = l0 * corr0 + sPart[r0] + sPart[64 + r0];
            l1 = l1 * corr1 + sPart[r1] + sPart[64 + r1];

#pragma unroll
            for (int t = 0; t < 16; t++) {
                oacc[t][0] *= corr0; oacc[t][1] *= corr0;
                oacc[t][2] *= corr1; oacc[t][3] *= corr1;
            }

            // ---- P fragments in-register ----
            uint32_t ph[2][4], pl[2][4];
#pragma unroll
            for (int c = 0; c < 2; c++) {
#pragma unroll
                for (int half = 0; half < 2; half++) {
                    const int nt = 2 * c + half;
                    float a0 = sacc[nt][0], a1 = sacc[nt][1];
                    float a2 = sacc[nt][2], a3 = sacc[nt][3];
                    __nv_bfloat16 h0 = __float2bfloat16(a0);
                    __nv_bfloat16 h1 = __float2bfloat16(a1);
                    __nv_bfloat16 h2 = __float2bfloat16(a2);
                    __nv_bfloat16 h3 = __float2bfloat16(a3);
                    ph[c][2 * half] =
                        (uint32_t)__bfloat16_as_ushort(h0) |
                        ((uint32_t)__bfloat16_as_ushort(h1) << 16);
                    ph[c][2 * half + 1] =
                        (uint32_t)__bfloat16_as_ushort(h2) |
                        ((uint32_t)__bfloat16_as_ushort(h3) << 16);
                    pl[c][2 * half] =
                        pack_bf(a0 - __bfloat162float(h0), a1 - __bfloat162float(h1));
                    pl[c][2 * half + 1] =
                        pack_bf(a2 - __bfloat162float(h2), a3 - __bfloat162float(h3));
                }
            }

            // ---- O += P V over this warp's 32 P-cols (3-term) ----
#pragma unroll
            for (int c = 0; c < 2; c++) {
                const uint32_t roff = (uint32_t)(((wh * 2 + c) * 16 + rk) * 256);
#pragma unroll
                for (int jp = 0; jp < 8; jp++) {
                    const int gq = jp * 2 + b3;
                    const uint32_t off = roff + (uint32_t)((gq ^ xr7) << 4);
                    uint32_t t0, t1, t2, t3, u0, u1, u2, u3;
                    LDSM4T(t0, t1, t2, t3, kvb + 32768 + off);
                    LDSM4T(u0, u1, u2, u3, kvb + 49152 + off);
                    uint32_t vh0[2] = {t0, t2}, vh1[2] = {t1, t3};
                    uint32_t vl0[2] = {u0, u2}, vl1[2] = {u1, u3};
                    MMA16816(oacc[2 * jp],     ph[c], vh0);
                    MMA16816(oacc[2 * jp],     ph[c], vl0);
                    MMA16816(oacc[2 * jp],     pl[c], vh0);
                    MMA16816(oacc[2 * jp + 1], ph[c], vh1);
                    MMA16816(oacc[2 * jp + 1], ph[c], vl1);
                    MMA16816(oacc[2 * jp + 1], pl[c], vh1);
                }
            }
            __syncthreads();
        }

        // ---- merge partial O between col-half partners, then store ----
        __syncthreads();                       // done reading KV smem
        if (wh == 1) {
            float* buf = (float*)(smA + AKV0 + wr * 8192);
#pragma unroll
            for (int t = 0; t < 16; t++) {
                const int col = t * 8 + tig * 2;
                *(float2*)&buf[g4 * 128 + col] =
                    make_float2(oacc[t][0], oacc[t][1]);
                *(float2*)&buf[(g4 + 8) * 128 + col] =
                    make_float2(oacc[t][2], oacc[t][3]);
            }
        }
        __syncthreads();
        if (wh == 0) {
            const float* buf = (const float*)(smA + AKV0 + wr * 8192);
            const float inv0 = 1.f / l0, inv1 = 1.f / l1;
#pragma unroll
            for (int t = 0; t < 16; t++) {
                const int col = t * 8 + tig * 2;
                float2 p0 = *(const float2*)&buf[g4 * 128 + col];
                float2 p1 = *(const float2*)&buf[(g4 + 8) * 128 + col];
                *(float2*)(out + qbase + (size_t)r0 * H_ + col) =
                    make_float2((oacc[t][0] + p0.x) * inv0,
                                (oacc[t][1] + p0.y) * inv0);
                *(float2*)(out + qbase + (size_t)r1 * H_ + col) =
                    make_float2((oacc[t][2] + p1.x) * inv1,
                                (oacc[t][3] + p1.y) * inv1);
            }
        }
    }
}

// ---------------------------------------------------------------------------
extern "C" void kernel_launch(void* const* d_in, const int* in_sizes, int n_in,
                              void* d_out, int out_size)
{
    const float* x  = (const float*)d_in[0];
    const float* Wq = (const float*)d_in[1];
    const float* Wk = (const float*)d_in[2];
    const float* Wv = (const float*)d_in[3];
    float* out = (float*)d_out;

    prep_w_kernel<<<384, 256>>>(Wq, Wk, Wv);
    prep_x_kernel<<<16384, 256>>>(x);

    cudaFuncSetAttribute(qkv_mma_kernel,
                         cudaFuncAttributeMaxDynamicSharedMemorySize, QK_SMEM);
    qkv_mma_kernel<<<dim3(128, 3), 256, QK_SMEM>>>();

    cudaFuncSetAttribute(attn_mma_kernel,
                         cudaFuncAttributeMaxDynamicSharedMemorySize, ATT_SMEM);
    attn_mma_kernel<<<dim3(16, 8), 256, ATT_SMEM>>>(out);
}